// round 9
// baseline (speedup 1.0000x reference)
#include <cuda_runtime.h>
#include <stdint.h>
#include <stddef.h>
#include <math.h>

#define BATCH 2
#define TLEN  2048
#define DM    1024
#define NH    16
#define DHD   64
#define BT    (BATCH * TLEN)   // 4096

// ---------------------------------------------------------------------------
// Scratch (allocation-free rule: __device__ globals)
// ---------------------------------------------------------------------------
__device__ float g_q[BT * DM];
__device__ float g_k[BT * DM];
__device__ float g_v[BT * DM];
__device__ float g_o[BT * DM];    // SIMT flash output (fallback / sampled)
__device__ float g_ot[BT * DM];   // tf32 flash output
__device__ float g_xc[BT * DM];
__device__ float g_wq[DM * DM];
__device__ float g_wk[DM * DM];
__device__ float g_wv[DM * DM];
__device__ float g_wo[DM * DM];
__device__ float g_diff2;
__device__ float g_ref2;
__device__ int   g_flag;          // 1 => tf32 flash accepted

// ---------------------------------------------------------------------------
// Helpers
// ---------------------------------------------------------------------------
__device__ __forceinline__ float f2tf32(float x) {
    uint32_t u;
    asm("cvt.rna.tf32.f32 %0, %1;" : "=r"(u) : "f"(x));
    return __uint_as_float(u);
}

__device__ __forceinline__ void cp16(uint32_t smem, const void* gmem) {
    asm volatile("cp.async.cg.shared.global [%0], [%1], 16;"
                 :: "r"(smem), "l"(gmem));
}
#define CP_COMMIT() asm volatile("cp.async.commit_group;")
#define CP_WAIT0()  asm volatile("cp.async.wait_group 0;")
#define CP_WAIT1()  asm volatile("cp.async.wait_group 1;")

#define MMA_TF32(d, a, b)                                                   \
    asm volatile(                                                           \
        "mma.sync.aligned.m16n8k8.row.col.f32.tf32.tf32.f32 "               \
        "{%0,%1,%2,%3},{%4,%5,%6,%7},{%8,%9},{%0,%1,%2,%3};"                \
        : "+f"((d)[0]), "+f"((d)[1]), "+f"((d)[2]), "+f"((d)[3])            \
        : "r"((a)[0]), "r"((a)[1]), "r"((a)[2]), "r"((a)[3]),               \
          "r"((b)[0]), "r"((b)[1]))

// ---------------------------------------------------------------------------
// Small utility kernels
// ---------------------------------------------------------------------------
__global__ void zero_stats() {
    g_diff2 = 0.0f; g_ref2 = 0.0f; g_flag = 0;
}

__global__ void cvt_tf32_kernel(const float4* __restrict__ in,
                                float4* __restrict__ out, int n4) {
    int i = blockIdx.x * blockDim.x + threadIdx.x;
    if (i < n4) {
        float4 v = in[i];
        v.x = f2tf32(v.x); v.y = f2tf32(v.y);
        v.z = f2tf32(v.z); v.w = f2tf32(v.w);
        out[i] = v;
    }
}

// Compare tf32 flash (a) vs sampled SIMT flash (b) over sampled rows.
// Sample: per batch, q-tiles 0 and 17 (64 rows each), all 1024 columns.
__global__ void compare_kernel(const float* __restrict__ a,
                               const float* __restrict__ b) {
    int gid = blockIdx.x * blockDim.x + threadIdx.x;
    float d2 = 0.0f, r2 = 0.0f;
    const int n = 2 * 2 * 64 * 1024;  // 262144
    for (int i = gid; i < n; i += gridDim.x * blockDim.x) {
        int c  = i & 1023;
        int r  = (i >> 10) & 63;
        int ti = (i >> 16) & 1;
        int bb = i >> 17;
        size_t row = (size_t)bb * TLEN + ti * 1088 + r;  // 17*64 = 1088
        float va = a[row * DM + c];
        float vb = b[row * DM + c];
        float d = va - vb;
        d2 += d * d;
        r2 += vb * vb;
    }
#pragma unroll
    for (int m = 16; m; m >>= 1) {
        d2 += __shfl_xor_sync(0xffffffffu, d2, m);
        r2 += __shfl_xor_sync(0xffffffffu, r2, m);
    }
    __shared__ float sd[8], sr[8];
    int lane = threadIdx.x & 31, w = threadIdx.x >> 5;
    if (lane == 0) { sd[w] = d2; sr[w] = r2; }
    __syncthreads();
    if (threadIdx.x == 0) {
        float td = 0.0f, tr = 0.0f;
#pragma unroll
        for (int i = 0; i < 8; i++) { td += sd[i]; tr += sr[i]; }
        atomicAdd(&g_diff2, td);
        atomicAdd(&g_ref2, tr);
    }
}

__global__ void decide_kernel() {
    // accept tf32 flash if relative L2 diff < 3e-3 (good ~2e-4, broken ~1)
    g_flag = (g_diff2 <= 9e-6f * g_ref2) ? 1 : 0;
}

// ---------------------------------------------------------------------------
// tf32 GEMM (NT): C[m,n] = sum_k A[m,k] * B[n,k]   (VERIFIED in R6)
// SEL: pick A at runtime by g_flag (A if accepted, Afb otherwise).
// ---------------------------------------------------------------------------
#define GS   36
#define GBUF (128 * GS)

template <bool CVT_OUT, bool SEL>
__global__ __launch_bounds__(128)
void gemm_tf32(const float* __restrict__ A, const float* __restrict__ Afb,
               const float* __restrict__ B, float* __restrict__ C,
               int M, int N, int K)
{
    if (SEL && g_flag == 0) A = Afb;

    extern __shared__ float sm[];
    float* As = sm;
    float* Bs = sm + 2 * GBUF;

    const int tid  = threadIdx.x;
    const int lane = tid & 31;
    const int warp = tid >> 5;
    const int g    = lane >> 2;
    const int t    = lane & 3;
    const int m0   = blockIdx.y * 128;
    const int n0   = blockIdx.x * 128;
    const int mw   = (warp >> 1) * 64;
    const int nw   = (warp & 1) * 64;

    const int lr = tid >> 3;
    const int lc = (tid & 7) << 2;
    const float* Ag = A + (size_t)(m0 + lr) * K + lc;
    const float* Bg = B + (size_t)(n0 + lr) * K + lc;

    const uint32_t sA = (uint32_t)__cvta_generic_to_shared(As);
    const uint32_t sB = (uint32_t)__cvta_generic_to_shared(Bs);
    const uint32_t soff = (uint32_t)(lr * GS + lc) * 4u;

    float acc[4][8][4];
#pragma unroll
    for (int mt = 0; mt < 4; mt++)
#pragma unroll
        for (int nt = 0; nt < 8; nt++)
#pragma unroll
            for (int r = 0; r < 4; r++) acc[mt][nt][r] = 0.0f;

    const int nkt = K >> 5;

#pragma unroll
    for (int i = 0; i < 8; i++) {
        cp16(sA + soff + (uint32_t)(i * 16 * GS * 4), Ag + (size_t)i * 16 * K);
        cp16(sB + soff + (uint32_t)(i * 16 * GS * 4), Bg + (size_t)i * 16 * K);
    }
    CP_COMMIT();

    for (int kt = 0; kt < nkt; kt++) {
        const int cur = kt & 1;
        if (kt + 1 < nkt) {
            const int nxt = cur ^ 1;
            const float* Ap = Ag + (size_t)(kt + 1) * 32;
            const float* Bp = Bg + (size_t)(kt + 1) * 32;
            const uint32_t bufo = (uint32_t)(nxt * GBUF * 4);
#pragma unroll
            for (int i = 0; i < 8; i++) {
                cp16(sA + bufo + soff + (uint32_t)(i * 16 * GS * 4), Ap + (size_t)i * 16 * K);
                cp16(sB + bufo + soff + (uint32_t)(i * 16 * GS * 4), Bp + (size_t)i * 16 * K);
            }
            CP_COMMIT();
            CP_WAIT1();
        } else {
            CP_WAIT0();
        }
        __syncthreads();

        const float* Ab = As + cur * GBUF + mw * GS;
        const float* Bb = Bs + cur * GBUF + nw * GS;
#pragma unroll
        for (int kc = 0; kc < 4; kc++) {
            const int kk = kc * 8;
            uint32_t af[4][4], bf[8][2];
#pragma unroll
            for (int mt = 0; mt < 4; mt++) {
                const float* p = Ab + (mt * 16 + g) * GS + kk + t;
                af[mt][0] = __float_as_uint(p[0]);
                af[mt][1] = __float_as_uint(p[8 * GS]);
                af[mt][2] = __float_as_uint(p[4]);
                af[mt][3] = __float_as_uint(p[8 * GS + 4]);
            }
#pragma unroll
            for (int nt = 0; nt < 8; nt++) {
                const float* p = Bb + (nt * 8 + g) * GS + kk + t;
                bf[nt][0] = __float_as_uint(p[0]);
                bf[nt][1] = __float_as_uint(p[4]);
            }
#pragma unroll
            for (int mt = 0; mt < 4; mt++)
#pragma unroll
                for (int nt = 0; nt < 8; nt++)
                    MMA_TF32(acc[mt][nt], af[mt], bf[nt]);
        }
        __syncthreads();
    }

#pragma unroll
    for (int mt = 0; mt < 4; mt++) {
#pragma unroll
        for (int nt = 0; nt < 8; nt++) {
            const int row = m0 + mw + mt * 16 + g;
            const int col = n0 + nw + nt * 8 + 2 * t;
            float2 v0, v1;
            if (CVT_OUT) {
                v0 = make_float2(f2tf32(acc[mt][nt][0]), f2tf32(acc[mt][nt][1]));
                v1 = make_float2(f2tf32(acc[mt][nt][2]), f2tf32(acc[mt][nt][3]));
            } else {
                v0 = make_float2(acc[mt][nt][0], acc[mt][nt][1]);
                v1 = make_float2(acc[mt][nt][2], acc[mt][nt][3]);
            }
            *(float2*)&C[(size_t)row * N + col]       = v0;
            *(float2*)&C[(size_t)(row + 8) * N + col] = v1;
        }
    }
}

// ---------------------------------------------------------------------------
// tf32 flash attention (rebuilt): block 128 thr (4 warps), Q tile 128,
// KV tile 64. Changes vs R5: block-wide __syncthreads() after P stores,
// P rounded RN to tf32.
// ---------------------------------------------------------------------------
#define QST 68
#define KST 68
#define VST 72
#define PST 68
#define FLASH_SMEM ((128 * QST + 64 * KST + 64 * VST + 128 * PST) * 4)  // 105472

__global__ __launch_bounds__(128)
void flash_tf32(const float* __restrict__ Q, const float* __restrict__ K,
                const float* __restrict__ V, float* __restrict__ O)
{
    extern __shared__ float sm[];
    float* Qs  = sm;                    // [128][QST]
    float* Ksm = Qs + 128 * QST;        // [64][KST]
    float* Vsm = Ksm + 64 * KST;        // [64][VST]
    float* Psm = Vsm + 64 * VST;        // [128][PST]

    const int tid  = threadIdx.x;
    const int lane = tid & 31;
    const int warp = tid >> 5;
    const int g    = lane >> 2;
    const int t    = lane & 3;
    const int q0   = blockIdx.x * 128;
    const int h    = blockIdx.y;
    const int b    = blockIdx.z;
    const size_t base = (size_t)b * TLEN * DM + (size_t)h * DHD;

    const int lr = tid >> 4;           // 0..7
    const int lc = (tid & 15) << 2;    // 0..60

#pragma unroll
    for (int i = 0; i < 16; i++) {
        const int row = lr + 8 * i;
        float4 v = *(const float4*)(Q + base + (size_t)(q0 + row) * DM + lc);
        v.x *= 0.125f; v.y *= 0.125f; v.z *= 0.125f; v.w *= 0.125f;
        *(float4*)&Qs[row * QST + lc] = v;
    }

    const int mw = warp * 32;

    float of[2][8][4];
#pragma unroll
    for (int mt = 0; mt < 2; mt++)
#pragma unroll
        for (int nt = 0; nt < 8; nt++)
#pragma unroll
            for (int r = 0; r < 4; r++) of[mt][nt][r] = 0.0f;

    float m_run[2][2] = {{-1e30f, -1e30f}, {-1e30f, -1e30f}};
    float l_run[2][2] = {{0.0f, 0.0f}, {0.0f, 0.0f}};

    const uint32_t sK = (uint32_t)__cvta_generic_to_shared(Ksm);
    const uint32_t sV = (uint32_t)__cvta_generic_to_shared(Vsm);

    for (int tk = 0; tk < TLEN / 64; tk++) {
        const int kv0 = tk * 64;
        __syncthreads();
#pragma unroll
        for (int i = 0; i < 8; i++) {
            const int row = lr + 8 * i;
            cp16(sK + (uint32_t)(row * KST + lc) * 4u,
                 K + base + (size_t)(kv0 + row) * DM + lc);
            cp16(sV + (uint32_t)(row * VST + lc) * 4u,
                 V + base + (size_t)(kv0 + row) * DM + lc);
        }
        CP_COMMIT();
        CP_WAIT0();
        __syncthreads();

        // ---- S = Q K^T ----
        float sf[2][8][4];
#pragma unroll
        for (int mt = 0; mt < 2; mt++)
#pragma unroll
            for (int nt = 0; nt < 8; nt++)
#pragma unroll
                for (int r = 0; r < 4; r++) sf[mt][nt][r] = 0.0f;

#pragma unroll
        for (int kc = 0; kc < 8; kc++) {
            const int kk = kc * 8;
            uint32_t qf[2][4], kb[8][2];
#pragma unroll
            for (int mt = 0; mt < 2; mt++) {
                const float* p = Qs + (mw + mt * 16 + g) * QST + kk + t;
                qf[mt][0] = __float_as_uint(p[0]);
                qf[mt][1] = __float_as_uint(p[8 * QST]);
                qf[mt][2] = __float_as_uint(p[4]);
                qf[mt][3] = __float_as_uint(p[8 * QST + 4]);
            }
#pragma unroll
            for (int nt = 0; nt < 8; nt++) {
                const float* p = Ksm + (nt * 8 + g) * KST + kk + t;
                kb[nt][0] = __float_as_uint(p[0]);
                kb[nt][1] = __float_as_uint(p[4]);
            }
#pragma unroll
            for (int mt = 0; mt < 2; mt++)
#pragma unroll
                for (int nt = 0; nt < 8; nt++)
                    MMA_TF32(sf[mt][nt], qf[mt], kb[nt]);
        }

        // ---- online softmax ----
#pragma unroll
        for (int mt = 0; mt < 2; mt++) {
#pragma unroll
            for (int rh = 0; rh < 2; rh++) {
                float mx = -1e30f;
#pragma unroll
                for (int nt = 0; nt < 8; nt++)
                    mx = fmaxf(mx, fmaxf(sf[mt][nt][rh * 2], sf[mt][nt][rh * 2 + 1]));
                mx = fmaxf(mx, __shfl_xor_sync(0xffffffffu, mx, 1));
                mx = fmaxf(mx, __shfl_xor_sync(0xffffffffu, mx, 2));
                const float newm = fmaxf(m_run[mt][rh], mx);
                const float fac  = __expf(m_run[mt][rh] - newm);
                float sum = 0.0f;
                float* prow = Psm + (mw + mt * 16 + g + rh * 8) * PST + 2 * t;
#pragma unroll
                for (int nt = 0; nt < 8; nt++) {
                    const float p0 = __expf(sf[mt][nt][rh * 2]     - newm);
                    const float p1 = __expf(sf[mt][nt][rh * 2 + 1] - newm);
                    sum += p0 + p1;
                    prow[nt * 8]     = f2tf32(p0);
                    prow[nt * 8 + 1] = f2tf32(p1);
                }
                sum += __shfl_xor_sync(0xffffffffu, sum, 1);
                sum += __shfl_xor_sync(0xffffffffu, sum, 2);
                l_run[mt][rh] = l_run[mt][rh] * fac + sum;
                m_run[mt][rh] = newm;
#pragma unroll
                for (int nt = 0; nt < 8; nt++) {
                    of[mt][nt][rh * 2]     *= fac;
                    of[mt][nt][rh * 2 + 1] *= fac;
                }
            }
        }
        __syncthreads();   // block-wide: P stores visible before PV

        // ---- O += P V ----
#pragma unroll
        for (int kc = 0; kc < 8; kc++) {
            const int kk = kc * 8;
            uint32_t pf[2][4], vb[8][2];
#pragma unroll
            for (int mt = 0; mt < 2; mt++) {
                const float* p = Psm + (mw + mt * 16 + g) * PST + kk + t;
                pf[mt][0] = __float_as_uint(p[0]);
                pf[mt][1] = __float_as_uint(p[8 * PST]);
                pf[mt][2] = __float_as_uint(p[4]);
                pf[mt][3] = __float_as_uint(p[8 * PST + 4]);
            }
#pragma unroll
            for (int nt = 0; nt < 8; nt++) {
                const float* p = Vsm + (kk + t) * VST + nt * 8 + g;
                vb[nt][0] = __float_as_uint(p[0]);
                vb[nt][1] = __float_as_uint(p[4 * VST]);
            }
#pragma unroll
            for (int mt = 0; mt < 2; mt++)
#pragma unroll
                for (int nt = 0; nt < 8; nt++)
                    MMA_TF32(of[mt][nt], pf[mt], vb[nt]);
        }
    }

#pragma unroll
    for (int mt = 0; mt < 2; mt++) {
#pragma unroll
        for (int rh = 0; rh < 2; rh++) {
            const float inv = 1.0f / l_run[mt][rh];
            const int row = q0 + mw + mt * 16 + g + rh * 8;
#pragma unroll
            for (int nt = 0; nt < 8; nt++) {
                const float a0 = f2tf32(of[mt][nt][rh * 2] * inv);
                const float a1 = f2tf32(of[mt][nt][rh * 2 + 1] * inv);
                *(float2*)&O[(size_t)row * DM + h * DHD + nt * 8 + 2 * t] =
                    make_float2(a0, a1);
            }
        }
    }
}

// ---------------------------------------------------------------------------
// SIMT flash (R3-verbatim logic). MODE 0: full, guarded by g_flag (early exit
// when tf32 accepted). MODE 1: sampled (q-tiles 0 and 17 per (b,h)).
// ---------------------------------------------------------------------------
#define FPAD 68

#define DOT4(qv, kv) ((qv).x * (kv).x + (qv).y * (kv).y + (qv).z * (kv).z + (qv).w * (kv).w)

#define SROW(i, qv)                       \
    s[i][0] += DOT4(qv, k0v);             \
    s[i][1] += DOT4(qv, k1v);             \
    s[i][2] += DOT4(qv, k2v);             \
    s[i][3] += DOT4(qv, k3v);

#define PV_U(comp, off)                                                     \
    do {                                                                    \
        const float* vr = &Vs[(j4 * 4 + (off)) * FPAD + tx];                \
        float v0 = vr[0], v1 = vr[16], v2 = vr[32], v3 = vr[48];            \
        o[0][0] = fmaf(p0.comp, v0, o[0][0]);                               \
        o[0][1] = fmaf(p0.comp, v1, o[0][1]);                               \
        o[0][2] = fmaf(p0.comp, v2, o[0][2]);                               \
        o[0][3] = fmaf(p0.comp, v3, o[0][3]);                               \
        o[1][0] = fmaf(p1.comp, v0, o[1][0]);                               \
        o[1][1] = fmaf(p1.comp, v1, o[1][1]);                               \
        o[1][2] = fmaf(p1.comp, v2, o[1][2]);                               \
        o[1][3] = fmaf(p1.comp, v3, o[1][3]);                               \
        o[2][0] = fmaf(p2.comp, v0, o[2][0]);                               \
        o[2][1] = fmaf(p2.comp, v1, o[2][1]);                               \
        o[2][2] = fmaf(p2.comp, v2, o[2][2]);                               \
        o[2][3] = fmaf(p2.comp, v3, o[2][3]);                               \
        o[3][0] = fmaf(p3.comp, v0, o[3][0]);                               \
        o[3][1] = fmaf(p3.comp, v1, o[3][1]);                               \
        o[3][2] = fmaf(p3.comp, v2, o[3][2]);                               \
        o[3][3] = fmaf(p3.comp, v3, o[3][3]);                               \
    } while (0)

template <int MODE>
__global__ __launch_bounds__(256)
void flash_simt(const float* __restrict__ Q, const float* __restrict__ K,
                const float* __restrict__ V, float* __restrict__ O)
{
    if (MODE == 0) {
        if (*(volatile int*)&g_flag) return;   // tf32 flash accepted
    }

    extern __shared__ float sm[];
    float* Qs = sm;
    float* Ks = sm + 64 * FPAD;
    float* Vs = sm + 2 * 64 * FPAD;
    float* Ps = sm + 3 * 64 * FPAD;

    const int tid = threadIdx.x;
    const int tx  = tid & 15;
    const int ty  = tid >> 4;
    const int q0  = (MODE == 0) ? blockIdx.x * 64 : blockIdx.x * 1088;  // tiles 0, 17
    const int h   = blockIdx.y;
    const int b   = blockIdx.z;
    const int base = b * TLEN * DM + h * DHD;

#pragma unroll
    for (int it = 0; it < 4; it++) {
        int f4 = tid + it * 256;
        int r  = f4 >> 4;
        int c4 = (f4 & 15) << 2;
        *(float4*)&Qs[r * FPAD + c4] =
            *(const float4*)(Q + base + (q0 + r) * DM + c4);
    }

    float m_run[4], l_run[4], o[4][4];
#pragma unroll
    for (int i = 0; i < 4; i++) {
        m_run[i] = -1e30f;
        l_run[i] = 0.0f;
#pragma unroll
        for (int j = 0; j < 4; j++) o[i][j] = 0.0f;
    }

    const float scale = 0.125f;

    for (int t = 0; t < TLEN / 64; t++) {
        __syncthreads();
        const int kv0 = t * 64;
#pragma unroll
        for (int it = 0; it < 4; it++) {
            int f4 = tid + it * 256;
            int r  = f4 >> 4;
            int c4 = (f4 & 15) << 2;
            *(float4*)&Ks[r * FPAD + c4] =
                *(const float4*)(K + base + (kv0 + r) * DM + c4);
            *(float4*)&Vs[r * FPAD + c4] =
                *(const float4*)(V + base + (kv0 + r) * DM + c4);
        }
        __syncthreads();

        float s[4][4];
#pragma unroll
        for (int i = 0; i < 4; i++)
#pragma unroll
            for (int j = 0; j < 4; j++) s[i][j] = 0.0f;

#pragma unroll
        for (int d4 = 0; d4 < 16; d4++) {
            float4 q0v = *(const float4*)&Qs[(ty * 4 + 0) * FPAD + d4 * 4];
            float4 q1v = *(const float4*)&Qs[(ty * 4 + 1) * FPAD + d4 * 4];
            float4 q2v = *(const float4*)&Qs[(ty * 4 + 2) * FPAD + d4 * 4];
            float4 q3v = *(const float4*)&Qs[(ty * 4 + 3) * FPAD + d4 * 4];
            float4 k0v = *(const float4*)&Ks[(tx +  0) * FPAD + d4 * 4];
            float4 k1v = *(const float4*)&Ks[(tx + 16) * FPAD + d4 * 4];
            float4 k2v = *(const float4*)&Ks[(tx + 32) * FPAD + d4 * 4];
            float4 k3v = *(const float4*)&Ks[(tx + 48) * FPAD + d4 * 4];
            SROW(0, q0v)
            SROW(1, q1v)
            SROW(2, q2v)
            SROW(3, q3v)
        }

#pragma unroll
        for (int i = 0; i < 4; i++) {
            float tmax = -1e30f;
#pragma unroll
            for (int j = 0; j < 4; j++) {
                s[i][j] *= scale;
                tmax = fmaxf(tmax, s[i][j]);
            }
#pragma unroll
            for (int msk = 1; msk < 16; msk <<= 1)
                tmax = fmaxf(tmax, __shfl_xor_sync(0xffffffffu, tmax, msk));
            float newm = fmaxf(m_run[i], tmax);
            float fac  = __expf(m_run[i] - newm);
            float tsum = 0.0f;
#pragma unroll
            for (int j = 0; j < 4; j++) {
                float p = __expf(s[i][j] - newm);
                tsum += p;
                Ps[(ty * 4 + i) * FPAD + tx + 16 * j] = p;
            }
#pragma unroll
            for (int msk = 1; msk < 16; msk <<= 1)
                tsum += __shfl_xor_sync(0xffffffffu, tsum, msk);
            l_run[i] = l_run[i] * fac + tsum;
            m_run[i] = newm;
#pragma unroll
            for (int j = 0; j < 4; j++) o[i][j] *= fac;
        }
        __syncthreads();

#pragma unroll
        for (int j4 = 0; j4 < 16; j4++) {
            float4 p0 = *(const float4*)&Ps[(ty * 4 + 0) * FPAD + j4 * 4];
            float4 p1 = *(const float4*)&Ps[(ty * 4 + 1) * FPAD + j4 * 4];
            float4 p2 = *(const float4*)&Ps[(ty * 4 + 2) * FPAD + j4 * 4];
            float4 p3 = *(const float4*)&Ps[(ty * 4 + 3) * FPAD + j4 * 4];
            PV_U(x, 0);
            PV_U(y, 1);
            PV_U(z, 2);
            PV_U(w, 3);
        }
    }

#pragma unroll
    for (int i = 0; i < 4; i++) {
        float inv = 1.0f / l_run[i];
        float* Op = O + base + (q0 + ty * 4 + i) * DM;
#pragma unroll
        for (int j = 0; j < 4; j++)
            Op[tx + 16 * j] = o[i][j] * inv;
    }
}

// ---------------------------------------------------------------------------
// Launch
// ---------------------------------------------------------------------------
extern "C" void kernel_launch(void* const* d_in, const int* in_sizes, int n_in,
                              void* d_out, int out_size)
{
    (void)in_sizes; (void)n_in; (void)out_size;
    const float* x  = (const float*)d_in[0];
    const float* Wq = (const float*)d_in[1];
    const float* Wk = (const float*)d_in[2];
    const float* Wv = (const float*)d_in[3];
    const float* Wo = (const float*)d_in[4];
    float* out = (float*)d_out;

    float *q, *k, *v, *o, *ot, *xc, *wq, *wk, *wv, *wo;
    cudaGetSymbolAddress((void**)&q,  g_q);
    cudaGetSymbolAddress((void**)&k,  g_k);
    cudaGetSymbolAddress((void**)&v,  g_v);
    cudaGetSymbolAddress((void**)&o,  g_o);
    cudaGetSymbolAddress((void**)&ot, g_ot);
    cudaGetSymbolAddress((void**)&xc, g_xc);
    cudaGetSymbolAddress((void**)&wq, g_wq);
    cudaGetSymbolAddress((void**)&wk, g_wk);
    cudaGetSymbolAddress((void**)&wv, g_wv);
    cudaGetSymbolAddress((void**)&wo, g_wo);

    const int gemm_smem = 4 * GBUF * (int)sizeof(float);        // 73728
    const int fl_smem   = 4 * 64 * FPAD * (int)sizeof(float);   // 69632

    cudaFuncSetAttribute(gemm_tf32<true, false>,
                         cudaFuncAttributeMaxDynamicSharedMemorySize, gemm_smem);
    cudaFuncSetAttribute(gemm_tf32<false, true>,
                         cudaFuncAttributeMaxDynamicSharedMemorySize, gemm_smem);
    cudaFuncSetAttribute(flash_tf32,
                         cudaFuncAttributeMaxDynamicSharedMemorySize, FLASH_SMEM);
    cudaFuncSetAttribute(flash_simt<0>,
                         cudaFuncAttributeMaxDynamicSharedMemorySize, fl_smem);
    cudaFuncSetAttribute(flash_simt<1>,
                         cudaFuncAttributeMaxDynamicSharedMemorySize, fl_smem);
    // max shared carveout -> allow 2 resident blocks (occupancy fix)
    cudaFuncSetAttribute(gemm_tf32<true, false>,
                         cudaFuncAttributePreferredSharedMemoryCarveout, 100);
    cudaFuncSetAttribute(gemm_tf32<false, true>,
                         cudaFuncAttributePreferredSharedMemoryCarveout, 100);
    cudaFuncSetAttribute(flash_simt<0>,
                         cudaFuncAttributePreferredSharedMemoryCarveout, 100);
    cudaFuncSetAttribute(flash_simt<1>,
                         cudaFuncAttributePreferredSharedMemoryCarveout, 100);
    cudaFuncSetAttribute(flash_tf32,
                         cudaFuncAttributePreferredSharedMemoryCarveout, 100);

    zero_stats<<<1, 1>>>();

    cvt_tf32_kernel<<<(BT * DM / 4 + 255) / 256, 256>>>((const float4*)x,  (float4*)xc, BT * DM / 4);
    cvt_tf32_kernel<<<(DM * DM / 4 + 255) / 256, 256>>>((const float4*)Wq, (float4*)wq, DM * DM / 4);
    cvt_tf32_kernel<<<(DM * DM / 4 + 255) / 256, 256>>>((const float4*)Wk, (float4*)wk, DM * DM / 4);
    cvt_tf32_kernel<<<(DM * DM / 4 + 255) / 256, 256>>>((const float4*)Wv, (float4*)wv, DM * DM / 4);
    cvt_tf32_kernel<<<(DM * DM / 4 + 255) / 256, 256>>>((const float4*)Wo, (float4*)wo, DM * DM / 4);

    dim3 gg(DM / 128, BT / 128);  // (8, 32)
    gemm_tf32<true, false><<<gg, 128, gemm_smem>>>(xc, nullptr, wq, q, BT, DM, DM);
    gemm_tf32<true, false><<<gg, 128, gemm_smem>>>(xc, nullptr, wk, k, BT, DM, DM);
    gemm_tf32<true, false><<<gg, 128, gemm_smem>>>(xc, nullptr, wv, v, BT, DM, DM);

    // candidate: tf32 tensor-core flash
    flash_tf32<<<dim3(TLEN / 128, NH, BATCH), 128, FLASH_SMEM>>>(q, k, v, ot);

    // sampled reference (proven SIMT path, 2 of 32 tiles per (b,h))
    flash_simt<1><<<dim3(2, NH, BATCH), 256, fl_smem>>>(q, k, v, o);

    compare_kernel<<<256, 256>>>(ot, o);
    decide_kernel<<<1, 1>>>();

    // fallback: full SIMT flash; early-exits if tf32 accepted
    flash_simt<0><<<dim3(TLEN / 64, NH, BATCH), 256, fl_smem>>>(q, k, v, o);

    // output projection; picks attention buffer by flag
    gemm_tf32<false, true><<<gg, 128, gemm_smem>>>(ot, o, wo, out, BT, DM, DM);
}

// round 10
// speedup vs baseline: 2.2907x; 2.2907x over previous
#include <cuda_runtime.h>
#include <stdint.h>
#include <stddef.h>
#include <math.h>

#define BATCH 2
#define TLEN  2048
#define DM    1024
#define NH    16
#define DHD   64
#define BT    (BATCH * TLEN)   // 4096

// ---------------------------------------------------------------------------
// Scratch (allocation-free rule: __device__ globals)
// ---------------------------------------------------------------------------
__device__ float g_q[BT * DM];
__device__ float g_k[BT * DM];
__device__ float g_v[BT * DM];
__device__ float g_o[BT * DM];    // SIMT flash output (fallback / sampled)
__device__ float g_ot[BT * DM];   // tf32 flash output
__device__ float g_xc[BT * DM];
__device__ float g_wq[DM * DM];
__device__ float g_wk[DM * DM];
__device__ float g_wv[DM * DM];
__device__ float g_wo[DM * DM];
__device__ float g_diff2;
__device__ float g_ref2;
__device__ int   g_flag;          // 1 => tf32 flash accepted

// ---------------------------------------------------------------------------
// Helpers
// ---------------------------------------------------------------------------
__device__ __forceinline__ float f2tf32(float x) {
    uint32_t u;
    asm("cvt.rna.tf32.f32 %0, %1;" : "=r"(u) : "f"(x));
    return __uint_as_float(u);
}

__device__ __forceinline__ void cp16(uint32_t smem, const void* gmem) {
    asm volatile("cp.async.cg.shared.global [%0], [%1], 16;"
                 :: "r"(smem), "l"(gmem));
}
#define CP_COMMIT() asm volatile("cp.async.commit_group;")
#define CP_WAIT0()  asm volatile("cp.async.wait_group 0;")
#define CP_WAIT1()  asm volatile("cp.async.wait_group 1;")

#define MMA_TF32(d, a, b)                                                   \
    asm volatile(                                                           \
        "mma.sync.aligned.m16n8k8.row.col.f32.tf32.tf32.f32 "               \
        "{%0,%1,%2,%3},{%4,%5,%6,%7},{%8,%9},{%0,%1,%2,%3};"                \
        : "+f"((d)[0]), "+f"((d)[1]), "+f"((d)[2]), "+f"((d)[3])            \
        : "r"((a)[0]), "r"((a)[1]), "r"((a)[2]), "r"((a)[3]),               \
          "r"((b)[0]), "r"((b)[1]))

// ---------------------------------------------------------------------------
// Small utility kernels
// ---------------------------------------------------------------------------
__global__ void zero_stats() {
    g_diff2 = 0.0f; g_ref2 = 0.0f; g_flag = 0;
}

__global__ void cvt_tf32_kernel(const float4* __restrict__ in,
                                float4* __restrict__ out, int n4) {
    int i = blockIdx.x * blockDim.x + threadIdx.x;
    if (i < n4) {
        float4 v = in[i];
        v.x = f2tf32(v.x); v.y = f2tf32(v.y);
        v.z = f2tf32(v.z); v.w = f2tf32(v.w);
        out[i] = v;
    }
}

// Compare tf32 flash (a) vs sampled SIMT flash (b) over sampled rows.
// Sample: per batch, q-tiles 0 and 17 (64 rows each), all 1024 columns.
__global__ void compare_kernel(const float* __restrict__ a,
                               const float* __restrict__ b) {
    int gid = blockIdx.x * blockDim.x + threadIdx.x;
    float d2 = 0.0f, r2 = 0.0f;
    const int n = 2 * 2 * 64 * 1024;  // 262144
    for (int i = gid; i < n; i += gridDim.x * blockDim.x) {
        int c  = i & 1023;
        int r  = (i >> 10) & 63;
        int ti = (i >> 16) & 1;
        int bb = i >> 17;
        size_t row = (size_t)bb * TLEN + ti * 1088 + r;  // 17*64 = 1088
        float va = a[row * DM + c];
        float vb = b[row * DM + c];
        float d = va - vb;
        d2 += d * d;
        r2 += vb * vb;
    }
#pragma unroll
    for (int m = 16; m; m >>= 1) {
        d2 += __shfl_xor_sync(0xffffffffu, d2, m);
        r2 += __shfl_xor_sync(0xffffffffu, r2, m);
    }
    __shared__ float sd[8], sr[8];
    int lane = threadIdx.x & 31, w = threadIdx.x >> 5;
    if (lane == 0) { sd[w] = d2; sr[w] = r2; }
    __syncthreads();
    if (threadIdx.x == 0) {
        float td = 0.0f, tr = 0.0f;
#pragma unroll
        for (int i = 0; i < 8; i++) { td += sd[i]; tr += sr[i]; }
        atomicAdd(&g_diff2, td);
        atomicAdd(&g_ref2, tr);
    }
}

__global__ void decide_kernel() {
    // accept tf32 flash if relative L2 diff < 3e-3 (good ~1e-4, broken ~1)
    g_flag = (g_diff2 <= 9e-6f * g_ref2) ? 1 : 0;
}

// ---------------------------------------------------------------------------
// tf32 GEMM (NT): C[m,n] = sum_k A[m,k] * B[n,k]   (VERIFIED in R6)
// SEL: pick A at runtime by g_flag (A if accepted, Afb otherwise).
// ---------------------------------------------------------------------------
#define GS   36
#define GBUF (128 * GS)

template <bool CVT_OUT, bool SEL>
__global__ __launch_bounds__(128)
void gemm_tf32(const float* __restrict__ A, const float* __restrict__ Afb,
               const float* __restrict__ B, float* __restrict__ C,
               int M, int N, int K)
{
    if (SEL && g_flag == 0) A = Afb;

    extern __shared__ float sm[];
    float* As = sm;
    float* Bs = sm + 2 * GBUF;

    const int tid  = threadIdx.x;
    const int lane = tid & 31;
    const int warp = tid >> 5;
    const int g    = lane >> 2;
    const int t    = lane & 3;
    const int m0   = blockIdx.y * 128;
    const int n0   = blockIdx.x * 128;
    const int mw   = (warp >> 1) * 64;
    const int nw   = (warp & 1) * 64;

    const int lr = tid >> 3;
    const int lc = (tid & 7) << 2;
    const float* Ag = A + (size_t)(m0 + lr) * K + lc;
    const float* Bg = B + (size_t)(n0 + lr) * K + lc;

    const uint32_t sA = (uint32_t)__cvta_generic_to_shared(As);
    const uint32_t sB = (uint32_t)__cvta_generic_to_shared(Bs);
    const uint32_t soff = (uint32_t)(lr * GS + lc) * 4u;

    float acc[4][8][4];
#pragma unroll
    for (int mt = 0; mt < 4; mt++)
#pragma unroll
        for (int nt = 0; nt < 8; nt++)
#pragma unroll
            for (int r = 0; r < 4; r++) acc[mt][nt][r] = 0.0f;

    const int nkt = K >> 5;

#pragma unroll
    for (int i = 0; i < 8; i++) {
        cp16(sA + soff + (uint32_t)(i * 16 * GS * 4), Ag + (size_t)i * 16 * K);
        cp16(sB + soff + (uint32_t)(i * 16 * GS * 4), Bg + (size_t)i * 16 * K);
    }
    CP_COMMIT();

    for (int kt = 0; kt < nkt; kt++) {
        const int cur = kt & 1;
        if (kt + 1 < nkt) {
            const int nxt = cur ^ 1;
            const float* Ap = Ag + (size_t)(kt + 1) * 32;
            const float* Bp = Bg + (size_t)(kt + 1) * 32;
            const uint32_t bufo = (uint32_t)(nxt * GBUF * 4);
#pragma unroll
            for (int i = 0; i < 8; i++) {
                cp16(sA + bufo + soff + (uint32_t)(i * 16 * GS * 4), Ap + (size_t)i * 16 * K);
                cp16(sB + bufo + soff + (uint32_t)(i * 16 * GS * 4), Bp + (size_t)i * 16 * K);
            }
            CP_COMMIT();
            CP_WAIT1();
        } else {
            CP_WAIT0();
        }
        __syncthreads();

        const float* Ab = As + cur * GBUF + mw * GS;
        const float* Bb = Bs + cur * GBUF + nw * GS;
#pragma unroll
        for (int kc = 0; kc < 4; kc++) {
            const int kk = kc * 8;
            uint32_t af[4][4], bf[8][2];
#pragma unroll
            for (int mt = 0; mt < 4; mt++) {
                const float* p = Ab + (mt * 16 + g) * GS + kk + t;
                af[mt][0] = __float_as_uint(p[0]);
                af[mt][1] = __float_as_uint(p[8 * GS]);
                af[mt][2] = __float_as_uint(p[4]);
                af[mt][3] = __float_as_uint(p[8 * GS + 4]);
            }
#pragma unroll
            for (int nt = 0; nt < 8; nt++) {
                const float* p = Bb + (nt * 8 + g) * GS + kk + t;
                bf[nt][0] = __float_as_uint(p[0]);
                bf[nt][1] = __float_as_uint(p[4]);
            }
#pragma unroll
            for (int mt = 0; mt < 4; mt++)
#pragma unroll
                for (int nt = 0; nt < 8; nt++)
                    MMA_TF32(acc[mt][nt], af[mt], bf[nt]);
        }
        __syncthreads();
    }

#pragma unroll
    for (int mt = 0; mt < 4; mt++) {
#pragma unroll
        for (int nt = 0; nt < 8; nt++) {
            const int row = m0 + mw + mt * 16 + g;
            const int col = n0 + nw + nt * 8 + 2 * t;
            float2 v0, v1;
            if (CVT_OUT) {
                v0 = make_float2(f2tf32(acc[mt][nt][0]), f2tf32(acc[mt][nt][1]));
                v1 = make_float2(f2tf32(acc[mt][nt][2]), f2tf32(acc[mt][nt][3]));
            } else {
                v0 = make_float2(acc[mt][nt][0], acc[mt][nt][1]);
                v1 = make_float2(acc[mt][nt][2], acc[mt][nt][3]);
            }
            *(float2*)&C[(size_t)row * N + col]       = v0;
            *(float2*)&C[(size_t)(row + 8) * N + col] = v1;
        }
    }
}

// ---------------------------------------------------------------------------
// tf32 flash attention. FIX vs R8: epilogue now includes the batch offset
// (writes through `O + base + row_local*DM`); R8 wrote batch 1 over batch 0
// and never touched batch 1's region.
// ---------------------------------------------------------------------------
#define QST 68
#define KST 68
#define VST 72
#define PST 68
#define FLASH_SMEM ((128 * QST + 64 * KST + 64 * VST + 128 * PST) * 4)  // 105472

__global__ __launch_bounds__(128)
void flash_tf32(const float* __restrict__ Q, const float* __restrict__ K,
                const float* __restrict__ V, float* __restrict__ O)
{
    extern __shared__ float sm[];
    float* Qs  = sm;                    // [128][QST]
    float* Ksm = Qs + 128 * QST;        // [64][KST]
    float* Vsm = Ksm + 64 * KST;        // [64][VST]
    float* Psm = Vsm + 64 * VST;        // [128][PST]

    const int tid  = threadIdx.x;
    const int lane = tid & 31;
    const int warp = tid >> 5;
    const int g    = lane >> 2;
    const int t    = lane & 3;
    const int q0   = blockIdx.x * 128;
    const int h    = blockIdx.y;
    const int b    = blockIdx.z;
    const size_t base = (size_t)b * TLEN * DM + (size_t)h * DHD;

    const int lr = tid >> 4;           // 0..7
    const int lc = (tid & 15) << 2;    // 0..60

#pragma unroll
    for (int i = 0; i < 16; i++) {
        const int row = lr + 8 * i;
        float4 v = *(const float4*)(Q + base + (size_t)(q0 + row) * DM + lc);
        v.x *= 0.125f; v.y *= 0.125f; v.z *= 0.125f; v.w *= 0.125f;
        *(float4*)&Qs[row * QST + lc] = v;
    }

    const int mw = warp * 32;

    float of[2][8][4];
#pragma unroll
    for (int mt = 0; mt < 2; mt++)
#pragma unroll
        for (int nt = 0; nt < 8; nt++)
#pragma unroll
            for (int r = 0; r < 4; r++) of[mt][nt][r] = 0.0f;

    float m_run[2][2] = {{-1e30f, -1e30f}, {-1e30f, -1e30f}};
    float l_run[2][2] = {{0.0f, 0.0f}, {0.0f, 0.0f}};

    const uint32_t sK = (uint32_t)__cvta_generic_to_shared(Ksm);
    const uint32_t sV = (uint32_t)__cvta_generic_to_shared(Vsm);

    for (int tk = 0; tk < TLEN / 64; tk++) {
        const int kv0 = tk * 64;
        __syncthreads();
#pragma unroll
        for (int i = 0; i < 8; i++) {
            const int row = lr + 8 * i;
            cp16(sK + (uint32_t)(row * KST + lc) * 4u,
                 K + base + (size_t)(kv0 + row) * DM + lc);
            cp16(sV + (uint32_t)(row * VST + lc) * 4u,
                 V + base + (size_t)(kv0 + row) * DM + lc);
        }
        CP_COMMIT();
        CP_WAIT0();
        __syncthreads();

        // ---- S = Q K^T ----
        float sf[2][8][4];
#pragma unroll
        for (int mt = 0; mt < 2; mt++)
#pragma unroll
            for (int nt = 0; nt < 8; nt++)
#pragma unroll
                for (int r = 0; r < 4; r++) sf[mt][nt][r] = 0.0f;

#pragma unroll
        for (int kc = 0; kc < 8; kc++) {
            const int kk = kc * 8;
            uint32_t qf[2][4], kb[8][2];
#pragma unroll
            for (int mt = 0; mt < 2; mt++) {
                const float* p = Qs + (mw + mt * 16 + g) * QST + kk + t;
                qf[mt][0] = __float_as_uint(p[0]);
                qf[mt][1] = __float_as_uint(p[8 * QST]);
                qf[mt][2] = __float_as_uint(p[4]);
                qf[mt][3] = __float_as_uint(p[8 * QST + 4]);
            }
#pragma unroll
            for (int nt = 0; nt < 8; nt++) {
                const float* p = Ksm + (nt * 8 + g) * KST + kk + t;
                kb[nt][0] = __float_as_uint(p[0]);
                kb[nt][1] = __float_as_uint(p[4]);
            }
#pragma unroll
            for (int mt = 0; mt < 2; mt++)
#pragma unroll
                for (int nt = 0; nt < 8; nt++)
                    MMA_TF32(sf[mt][nt], qf[mt], kb[nt]);
        }

        // ---- online softmax ----
#pragma unroll
        for (int mt = 0; mt < 2; mt++) {
#pragma unroll
            for (int rh = 0; rh < 2; rh++) {
                float mx = -1e30f;
#pragma unroll
                for (int nt = 0; nt < 8; nt++)
                    mx = fmaxf(mx, fmaxf(sf[mt][nt][rh * 2], sf[mt][nt][rh * 2 + 1]));
                mx = fmaxf(mx, __shfl_xor_sync(0xffffffffu, mx, 1));
                mx = fmaxf(mx, __shfl_xor_sync(0xffffffffu, mx, 2));
                const float newm = fmaxf(m_run[mt][rh], mx);
                const float fac  = __expf(m_run[mt][rh] - newm);
                float sum = 0.0f;
                float* prow = Psm + (mw + mt * 16 + g + rh * 8) * PST + 2 * t;
#pragma unroll
                for (int nt = 0; nt < 8; nt++) {
                    const float p0 = __expf(sf[mt][nt][rh * 2]     - newm);
                    const float p1 = __expf(sf[mt][nt][rh * 2 + 1] - newm);
                    sum += p0 + p1;
                    prow[nt * 8]     = f2tf32(p0);
                    prow[nt * 8 + 1] = f2tf32(p1);
                }
                sum += __shfl_xor_sync(0xffffffffu, sum, 1);
                sum += __shfl_xor_sync(0xffffffffu, sum, 2);
                l_run[mt][rh] = l_run[mt][rh] * fac + sum;
                m_run[mt][rh] = newm;
#pragma unroll
                for (int nt = 0; nt < 8; nt++) {
                    of[mt][nt][rh * 2]     *= fac;
                    of[mt][nt][rh * 2 + 1] *= fac;
                }
            }
        }
        __syncthreads();   // P stores visible before PV

        // ---- O += P V ----
#pragma unroll
        for (int kc = 0; kc < 8; kc++) {
            const int kk = kc * 8;
            uint32_t pf[2][4], vb[8][2];
#pragma unroll
            for (int mt = 0; mt < 2; mt++) {
                const float* p = Psm + (mw + mt * 16 + g) * PST + kk + t;
                pf[mt][0] = __float_as_uint(p[0]);
                pf[mt][1] = __float_as_uint(p[8 * PST]);
                pf[mt][2] = __float_as_uint(p[4]);
                pf[mt][3] = __float_as_uint(p[8 * PST + 4]);
            }
#pragma unroll
            for (int nt = 0; nt < 8; nt++) {
                const float* p = Vsm + (kk + t) * VST + nt * 8 + g;
                vb[nt][0] = __float_as_uint(p[0]);
                vb[nt][1] = __float_as_uint(p[4 * VST]);
            }
#pragma unroll
            for (int mt = 0; mt < 2; mt++)
#pragma unroll
                for (int nt = 0; nt < 8; nt++)
                    MMA_TF32(of[mt][nt], pf[mt], vb[nt]);
        }
    }

    // ---- epilogue (FIXED: include batch offset via `base`) ----
#pragma unroll
    for (int mt = 0; mt < 2; mt++) {
#pragma unroll
        for (int rh = 0; rh < 2; rh++) {
            const float inv = 1.0f / l_run[mt][rh];
            const int rloc = q0 + mw + mt * 16 + g + rh * 8;
            float* Op = O + base + (size_t)rloc * DM;
#pragma unroll
            for (int nt = 0; nt < 8; nt++) {
                const float a0 = f2tf32(of[mt][nt][rh * 2] * inv);
                const float a1 = f2tf32(of[mt][nt][rh * 2 + 1] * inv);
                *(float2*)&Op[nt * 8 + 2 * t] = make_float2(a0, a1);
            }
        }
    }
}

// ---------------------------------------------------------------------------
// SIMT flash (R3-verbatim logic). MODE 0: full, guarded by g_flag (early exit
// when tf32 accepted). MODE 1: sampled (q-tiles 0 and 17 per (b,h)).
// ---------------------------------------------------------------------------
#define FPAD 68

#define DOT4(qv, kv) ((qv).x * (kv).x + (qv).y * (kv).y + (qv).z * (kv).z + (qv).w * (kv).w)

#define SROW(i, qv)                       \
    s[i][0] += DOT4(qv, k0v);             \
    s[i][1] += DOT4(qv, k1v);             \
    s[i][2] += DOT4(qv, k2v);             \
    s[i][3] += DOT4(qv, k3v);

#define PV_U(comp, off)                                                     \
    do {                                                                    \
        const float* vr = &Vs[(j4 * 4 + (off)) * FPAD + tx];                \
        float v0 = vr[0], v1 = vr[16], v2 = vr[32], v3 = vr[48];            \
        o[0][0] = fmaf(p0.comp, v0, o[0][0]);                               \
        o[0][1] = fmaf(p0.comp, v1, o[0][1]);                               \
        o[0][2] = fmaf(p0.comp, v2, o[0][2]);                               \
        o[0][3] = fmaf(p0.comp, v3, o[0][3]);                               \
        o[1][0] = fmaf(p1.comp, v0, o[1][0]);                               \
        o[1][1] = fmaf(p1.comp, v1, o[1][1]);                               \
        o[1][2] = fmaf(p1.comp, v2, o[1][2]);                               \
        o[1][3] = fmaf(p1.comp, v3, o[1][3]);                               \
        o[2][0] = fmaf(p2.comp, v0, o[2][0]);                               \
        o[2][1] = fmaf(p2.comp, v1, o[2][1]);                               \
        o[2][2] = fmaf(p2.comp, v2, o[2][2]);                               \
        o[2][3] = fmaf(p2.comp, v3, o[2][3]);                               \
        o[3][0] = fmaf(p3.comp, v0, o[3][0]);                               \
        o[3][1] = fmaf(p3.comp, v1, o[3][1]);                               \
        o[3][2] = fmaf(p3.comp, v2, o[3][2]);                               \
        o[3][3] = fmaf(p3.comp, v3, o[3][3]);                               \
    } while (0)

template <int MODE>
__global__ __launch_bounds__(256)
void flash_simt(const float* __restrict__ Q, const float* __restrict__ K,
                const float* __restrict__ V, float* __restrict__ O)
{
    if (MODE == 0) {
        if (*(volatile int*)&g_flag) return;   // tf32 flash accepted
    }

    extern __shared__ float sm[];
    float* Qs = sm;
    float* Ks = sm + 64 * FPAD;
    float* Vs = sm + 2 * 64 * FPAD;
    float* Ps = sm + 3 * 64 * FPAD;

    const int tid = threadIdx.x;
    const int tx  = tid & 15;
    const int ty  = tid >> 4;
    const int q0  = (MODE == 0) ? blockIdx.x * 64 : blockIdx.x * 1088;  // tiles 0, 17
    const int h   = blockIdx.y;
    const int b   = blockIdx.z;
    const int base = b * TLEN * DM + h * DHD;

#pragma unroll
    for (int it = 0; it < 4; it++) {
        int f4 = tid + it * 256;
        int r  = f4 >> 4;
        int c4 = (f4 & 15) << 2;
        *(float4*)&Qs[r * FPAD + c4] =
            *(const float4*)(Q + base + (q0 + r) * DM + c4);
    }

    float m_run[4], l_run[4], o[4][4];
#pragma unroll
    for (int i = 0; i < 4; i++) {
        m_run[i] = -1e30f;
        l_run[i] = 0.0f;
#pragma unroll
        for (int j = 0; j < 4; j++) o[i][j] = 0.0f;
    }

    const float scale = 0.125f;

    for (int t = 0; t < TLEN / 64; t++) {
        __syncthreads();
        const int kv0 = t * 64;
#pragma unroll
        for (int it = 0; it < 4; it++) {
            int f4 = tid + it * 256;
            int r  = f4 >> 4;
            int c4 = (f4 & 15) << 2;
            *(float4*)&Ks[r * FPAD + c4] =
                *(const float4*)(K + base + (kv0 + r) * DM + c4);
            *(float4*)&Vs[r * FPAD + c4] =
                *(const float4*)(V + base + (kv0 + r) * DM + c4);
        }
        __syncthreads();

        float s[4][4];
#pragma unroll
        for (int i = 0; i < 4; i++)
#pragma unroll
            for (int j = 0; j < 4; j++) s[i][j] = 0.0f;

#pragma unroll
        for (int d4 = 0; d4 < 16; d4++) {
            float4 q0v = *(const float4*)&Qs[(ty * 4 + 0) * FPAD + d4 * 4];
            float4 q1v = *(const float4*)&Qs[(ty * 4 + 1) * FPAD + d4 * 4];
            float4 q2v = *(const float4*)&Qs[(ty * 4 + 2) * FPAD + d4 * 4];
            float4 q3v = *(const float4*)&Qs[(ty * 4 + 3) * FPAD + d4 * 4];
            float4 k0v = *(const float4*)&Ks[(tx +  0) * FPAD + d4 * 4];
            float4 k1v = *(const float4*)&Ks[(tx + 16) * FPAD + d4 * 4];
            float4 k2v = *(const float4*)&Ks[(tx + 32) * FPAD + d4 * 4];
            float4 k3v = *(const float4*)&Ks[(tx + 48) * FPAD + d4 * 4];
            SROW(0, q0v)
            SROW(1, q1v)
            SROW(2, q2v)
            SROW(3, q3v)
        }

#pragma unroll
        for (int i = 0; i < 4; i++) {
            float tmax = -1e30f;
#pragma unroll
            for (int j = 0; j < 4; j++) {
                s[i][j] *= scale;
                tmax = fmaxf(tmax, s[i][j]);
            }
#pragma unroll
            for (int msk = 1; msk < 16; msk <<= 1)
                tmax = fmaxf(tmax, __shfl_xor_sync(0xffffffffu, tmax, msk));
            float newm = fmaxf(m_run[i], tmax);
            float fac  = __expf(m_run[i] - newm);
            float tsum = 0.0f;
#pragma unroll
            for (int j = 0; j < 4; j++) {
                float p = __expf(s[i][j] - newm);
                tsum += p;
                Ps[(ty * 4 + i) * FPAD + tx + 16 * j] = p;
            }
#pragma unroll
            for (int msk = 1; msk < 16; msk <<= 1)
                tsum += __shfl_xor_sync(0xffffffffu, tsum, msk);
            l_run[i] = l_run[i] * fac + tsum;
            m_run[i] = newm;
#pragma unroll
            for (int j = 0; j < 4; j++) o[i][j] *= fac;
        }
        __syncthreads();

#pragma unroll
        for (int j4 = 0; j4 < 16; j4++) {
            float4 p0 = *(const float4*)&Ps[(ty * 4 + 0) * FPAD + j4 * 4];
            float4 p1 = *(const float4*)&Ps[(ty * 4 + 1) * FPAD + j4 * 4];
            float4 p2 = *(const float4*)&Ps[(ty * 4 + 2) * FPAD + j4 * 4];
            float4 p3 = *(const float4*)&Ps[(ty * 4 + 3) * FPAD + j4 * 4];
            PV_U(x, 0);
            PV_U(y, 1);
            PV_U(z, 2);
            PV_U(w, 3);
        }
    }

#pragma unroll
    for (int i = 0; i < 4; i++) {
        float inv = 1.0f / l_run[i];
        float* Op = O + base + (q0 + ty * 4 + i) * DM;
#pragma unroll
        for (int j = 0; j < 4; j++)
            Op[tx + 16 * j] = o[i][j] * inv;
    }
}

// ---------------------------------------------------------------------------
// Launch
// ---------------------------------------------------------------------------
extern "C" void kernel_launch(void* const* d_in, const int* in_sizes, int n_in,
                              void* d_out, int out_size)
{
    (void)in_sizes; (void)n_in; (void)out_size;
    const float* x  = (const float*)d_in[0];
    const float* Wq = (const float*)d_in[1];
    const float* Wk = (const float*)d_in[2];
    const float* Wv = (const float*)d_in[3];
    const float* Wo = (const float*)d_in[4];
    float* out = (float*)d_out;

    float *q, *k, *v, *o, *ot, *xc, *wq, *wk, *wv, *wo;
    cudaGetSymbolAddress((void**)&q,  g_q);
    cudaGetSymbolAddress((void**)&k,  g_k);
    cudaGetSymbolAddress((void**)&v,  g_v);
    cudaGetSymbolAddress((void**)&o,  g_o);
    cudaGetSymbolAddress((void**)&ot, g_ot);
    cudaGetSymbolAddress((void**)&xc, g_xc);
    cudaGetSymbolAddress((void**)&wq, g_wq);
    cudaGetSymbolAddress((void**)&wk, g_wk);
    cudaGetSymbolAddress((void**)&wv, g_wv);
    cudaGetSymbolAddress((void**)&wo, g_wo);

    const int gemm_smem = 4 * GBUF * (int)sizeof(float);        // 73728
    const int fl_smem   = 4 * 64 * FPAD * (int)sizeof(float);   // 69632

    cudaFuncSetAttribute(gemm_tf32<true, false>,
                         cudaFuncAttributeMaxDynamicSharedMemorySize, gemm_smem);
    cudaFuncSetAttribute(gemm_tf32<false, true>,
                         cudaFuncAttributeMaxDynamicSharedMemorySize, gemm_smem);
    cudaFuncSetAttribute(flash_tf32,
                         cudaFuncAttributeMaxDynamicSharedMemorySize, FLASH_SMEM);
    cudaFuncSetAttribute(flash_simt<0>,
                         cudaFuncAttributeMaxDynamicSharedMemorySize, fl_smem);
    cudaFuncSetAttribute(flash_simt<1>,
                         cudaFuncAttributeMaxDynamicSharedMemorySize, fl_smem);
    cudaFuncSetAttribute(gemm_tf32<true, false>,
                         cudaFuncAttributePreferredSharedMemoryCarveout, 100);
    cudaFuncSetAttribute(gemm_tf32<false, true>,
                         cudaFuncAttributePreferredSharedMemoryCarveout, 100);
    cudaFuncSetAttribute(flash_simt<0>,
                         cudaFuncAttributePreferredSharedMemoryCarveout, 100);
    cudaFuncSetAttribute(flash_simt<1>,
                         cudaFuncAttributePreferredSharedMemoryCarveout, 100);
    cudaFuncSetAttribute(flash_tf32,
                         cudaFuncAttributePreferredSharedMemoryCarveout, 100);

    zero_stats<<<1, 1>>>();

    cvt_tf32_kernel<<<(BT * DM / 4 + 255) / 256, 256>>>((const float4*)x,  (float4*)xc, BT * DM / 4);
    cvt_tf32_kernel<<<(DM * DM / 4 + 255) / 256, 256>>>((const float4*)Wq, (float4*)wq, DM * DM / 4);
    cvt_tf32_kernel<<<(DM * DM / 4 + 255) / 256, 256>>>((const float4*)Wk, (float4*)wk, DM * DM / 4);
    cvt_tf32_kernel<<<(DM * DM / 4 + 255) / 256, 256>>>((const float4*)Wv, (float4*)wv, DM * DM / 4);
    cvt_tf32_kernel<<<(DM * DM / 4 + 255) / 256, 256>>>((const float4*)Wo, (float4*)wo, DM * DM / 4);

    dim3 gg(DM / 128, BT / 128);  // (8, 32)
    gemm_tf32<true, false><<<gg, 128, gemm_smem>>>(xc, nullptr, wq, q, BT, DM, DM);
    gemm_tf32<true, false><<<gg, 128, gemm_smem>>>(xc, nullptr, wk, k, BT, DM, DM);
    gemm_tf32<true, false><<<gg, 128, gemm_smem>>>(xc, nullptr, wv, v, BT, DM, DM);

    // candidate: tf32 tensor-core flash
    flash_tf32<<<dim3(TLEN / 128, NH, BATCH), 128, FLASH_SMEM>>>(q, k, v, ot);

    // sampled reference (proven SIMT path, 2 of 32 tiles per (b,h))
    flash_simt<1><<<dim3(2, NH, BATCH), 256, fl_smem>>>(q, k, v, o);

    compare_kernel<<<256, 256>>>(ot, o);
    decide_kernel<<<1, 1>>>();

    // fallback: full SIMT flash; early-exits if tf32 accepted
    flash_simt<0><<<dim3(TLEN / 64, NH, BATCH), 256, fl_smem>>>(q, k, v, o);

    // output projection; picks attention buffer by flag
    gemm_tf32<false, true><<<gg, 128, gemm_smem>>>(ot, o, wo, out, BT, DM, DM);
}

// round 12
// speedup vs baseline: 2.8968x; 1.2646x over previous
#include <cuda_runtime.h>
#include <stdint.h>
#include <stddef.h>
#include <math.h>

#define BATCH 2
#define TLEN  2048
#define DM    1024
#define NH    16
#define DHD   64
#define BT    (BATCH * TLEN)   // 4096

// ---------------------------------------------------------------------------
// Scratch (allocation-free rule: __device__ globals)
// ---------------------------------------------------------------------------
__device__ float g_q[BT * DM];
__device__ float g_k[BT * DM];
__device__ float g_v[BT * DM];
__device__ float g_ot[BT * DM];   // attention output
__device__ float g_xc[BT * DM];
__device__ float g_wq[DM * DM];
__device__ float g_wk[DM * DM];
__device__ float g_wv[DM * DM];
__device__ float g_wo[DM * DM];

// ---------------------------------------------------------------------------
// Helpers
// ---------------------------------------------------------------------------
__device__ __forceinline__ float f2tf32(float x) {
    uint32_t u;
    asm("cvt.rna.tf32.f32 %0, %1;" : "=r"(u) : "f"(x));
    return __uint_as_float(u);
}

__device__ __forceinline__ void cp16(uint32_t smem, const void* gmem) {
    asm volatile("cp.async.cg.shared.global [%0], [%1], 16;"
                 :: "r"(smem), "l"(gmem));
}
#define CP_COMMIT() asm volatile("cp.async.commit_group;")
#define CP_WAIT0()  asm volatile("cp.async.wait_group 0;")
#define CP_WAIT1()  asm volatile("cp.async.wait_group 1;")

// mma.sync m16n8k8 tf32 (layouts hardware-verified in R6/R9)
#define MMA_TF32(d, a, b)                                                   \
    asm volatile(                                                           \
        "mma.sync.aligned.m16n8k8.row.col.f32.tf32.tf32.f32 "               \
        "{%0,%1,%2,%3},{%4,%5,%6,%7},{%8,%9},{%0,%1,%2,%3};"                \
        : "+f"((d)[0]), "+f"((d)[1]), "+f"((d)[2]), "+f"((d)[3])            \
        : "r"((a)[0]), "r"((a)[1]), "r"((a)[2]), "r"((a)[3]),               \
          "r"((b)[0]), "r"((b)[1]))

// ---------------------------------------------------------------------------
// Prep: round fp32 -> tf32 (RN) into scratch
// ---------------------------------------------------------------------------
__global__ void cvt_tf32_kernel(const float4* __restrict__ in,
                                float4* __restrict__ out, int n4) {
    int i = blockIdx.x * blockDim.x + threadIdx.x;
    if (i < n4) {
        float4 v = in[i];
        v.x = f2tf32(v.x); v.y = f2tf32(v.y);
        v.z = f2tf32(v.z); v.w = f2tf32(v.w);
        out[i] = v;
    }
}

// ---------------------------------------------------------------------------
// tf32 GEMM (NT): C[m,n] = sum_k A[m,k] * B[n,k]   (VERIFIED)
// QKV: templated on source of B/C via blockIdx.z (fused 3-GEMM launch).
// ---------------------------------------------------------------------------
#define GS   36
#define GBUF (128 * GS)

template <bool CVT_OUT, bool QKV>
__global__ __launch_bounds__(128)
void gemm_tf32(const float* __restrict__ A,
               const float* __restrict__ B0, const float* __restrict__ B1,
               const float* __restrict__ B2,
               float* __restrict__ C0, float* __restrict__ C1,
               float* __restrict__ C2,
               int M, int N, int K)
{
    const float* B = B0;
    float* C = C0;
    if (QKV) {
        if (blockIdx.z == 1) { B = B1; C = C1; }
        else if (blockIdx.z == 2) { B = B2; C = C2; }
    }

    extern __shared__ float sm[];
    float* As = sm;
    float* Bs = sm + 2 * GBUF;

    const int tid  = threadIdx.x;
    const int lane = tid & 31;
    const int warp = tid >> 5;
    const int g    = lane >> 2;
    const int t    = lane & 3;
    const int m0   = blockIdx.y * 128;
    const int n0   = blockIdx.x * 128;
    const int mw   = (warp >> 1) * 64;
    const int nw   = (warp & 1) * 64;

    const int lr = tid >> 3;
    const int lc = (tid & 7) << 2;
    const float* Ag = A + (size_t)(m0 + lr) * K + lc;
    const float* Bg = B + (size_t)(n0 + lr) * K + lc;

    const uint32_t sA = (uint32_t)__cvta_generic_to_shared(As);
    const uint32_t sB = (uint32_t)__cvta_generic_to_shared(Bs);
    const uint32_t soff = (uint32_t)(lr * GS + lc) * 4u;

    float acc[4][8][4];
#pragma unroll
    for (int mt = 0; mt < 4; mt++)
#pragma unroll
        for (int nt = 0; nt < 8; nt++)
#pragma unroll
            for (int r = 0; r < 4; r++) acc[mt][nt][r] = 0.0f;

    const int nkt = K >> 5;

#pragma unroll
    for (int i = 0; i < 8; i++) {
        cp16(sA + soff + (uint32_t)(i * 16 * GS * 4), Ag + (size_t)i * 16 * K);
        cp16(sB + soff + (uint32_t)(i * 16 * GS * 4), Bg + (size_t)i * 16 * K);
    }
    CP_COMMIT();

    for (int kt = 0; kt < nkt; kt++) {
        const int cur = kt & 1;
        if (kt + 1 < nkt) {
            const int nxt = cur ^ 1;
            const float* Ap = Ag + (size_t)(kt + 1) * 32;
            const float* Bp = Bg + (size_t)(kt + 1) * 32;
            const uint32_t bufo = (uint32_t)(nxt * GBUF * 4);
#pragma unroll
            for (int i = 0; i < 8; i++) {
                cp16(sA + bufo + soff + (uint32_t)(i * 16 * GS * 4), Ap + (size_t)i * 16 * K);
                cp16(sB + bufo + soff + (uint32_t)(i * 16 * GS * 4), Bp + (size_t)i * 16 * K);
            }
            CP_COMMIT();
            CP_WAIT1();
        } else {
            CP_WAIT0();
        }
        __syncthreads();

        const float* Ab = As + cur * GBUF + mw * GS;
        const float* Bb = Bs + cur * GBUF + nw * GS;
#pragma unroll
        for (int kc = 0; kc < 4; kc++) {
            const int kk = kc * 8;
            uint32_t af[4][4], bf[8][2];
#pragma unroll
            for (int mt = 0; mt < 4; mt++) {
                const float* p = Ab + (mt * 16 + g) * GS + kk + t;
                af[mt][0] = __float_as_uint(p[0]);
                af[mt][1] = __float_as_uint(p[8 * GS]);
                af[mt][2] = __float_as_uint(p[4]);
                af[mt][3] = __float_as_uint(p[8 * GS + 4]);
            }
#pragma unroll
            for (int nt = 0; nt < 8; nt++) {
                const float* p = Bb + (nt * 8 + g) * GS + kk + t;
                bf[nt][0] = __float_as_uint(p[0]);
                bf[nt][1] = __float_as_uint(p[4]);
            }
#pragma unroll
            for (int mt = 0; mt < 4; mt++)
#pragma unroll
                for (int nt = 0; nt < 8; nt++)
                    MMA_TF32(acc[mt][nt], af[mt], bf[nt]);
        }
        __syncthreads();
    }

#pragma unroll
    for (int mt = 0; mt < 4; mt++) {
#pragma unroll
        for (int nt = 0; nt < 8; nt++) {
            const int row = m0 + mw + mt * 16 + g;
            const int col = n0 + nw + nt * 8 + 2 * t;
            float2 v0, v1;
            if (CVT_OUT) {
                v0 = make_float2(f2tf32(acc[mt][nt][0]), f2tf32(acc[mt][nt][1]));
                v1 = make_float2(f2tf32(acc[mt][nt][2]), f2tf32(acc[mt][nt][3]));
            } else {
                v0 = make_float2(acc[mt][nt][0], acc[mt][nt][1]);
                v1 = make_float2(acc[mt][nt][2], acc[mt][nt][3]);
            }
            *(float2*)&C[(size_t)row * N + col]       = v0;
            *(float2*)&C[(size_t)(row + 8) * N + col] = v1;
        }
    }
}

// ---------------------------------------------------------------------------
// tf32 flash attention v2: 256 threads (8 warps), Q tile 128 (16 rows/warp),
// KV tile 64, double-buffered cp.async K/V. Same verified fragment layouts
// and smem strides (conflict-free). P warp-private -> __syncwarp().
// ---------------------------------------------------------------------------
#define QST 68
#define KST 68
#define VST 72
#define PST 68
#define KBUF (64 * KST)
#define VBUF (64 * VST)
// Qs + 2*K + 2*V + Ps
#define FLASH_SMEM ((128 * QST + 2 * KBUF + 2 * VBUF + 128 * PST) * 4)  // 141312

__global__ __launch_bounds__(256)
void flash_tf32(const float* __restrict__ Q, const float* __restrict__ K,
                const float* __restrict__ V, float* __restrict__ O)
{
    extern __shared__ float sm[];
    float* Qs  = sm;                      // [128][QST]
    float* Ksm = Qs + 128 * QST;          // [2][64][KST]
    float* Vsm = Ksm + 2 * KBUF;          // [2][64][VST]
    float* Psm = Vsm + 2 * VBUF;          // [128][PST]

    const int tid  = threadIdx.x;
    const int lane = tid & 31;
    const int warp = tid >> 5;            // 0..7
    const int g    = lane >> 2;
    const int t    = lane & 3;
    const int q0   = blockIdx.x * 128;
    const int h    = blockIdx.y;
    const int b    = blockIdx.z;
    const size_t base = (size_t)b * TLEN * DM + (size_t)h * DHD;

    // loader: 256 threads -> (row lr + 16*i, cols lc..lc+3), 64-wide rows
    const int lr = tid >> 4;              // 0..15
    const int lc = (tid & 15) << 2;       // 0..60

    // load Q tile (128 x 64), pre-scaled by 1/sqrt(64) (exact in tf32)
#pragma unroll
    for (int i = 0; i < 8; i++) {
        const int row = lr + 16 * i;
        float4 v = *(const float4*)(Q + base + (size_t)(q0 + row) * DM + lc);
        v.x *= 0.125f; v.y *= 0.125f; v.z *= 0.125f; v.w *= 0.125f;
        *(float4*)&Qs[row * QST + lc] = v;
    }

    const int mw = warp * 16;             // 16 Q-rows per warp

    float of[8][4];
#pragma unroll
    for (int nt = 0; nt < 8; nt++)
#pragma unroll
        for (int r = 0; r < 4; r++) of[nt][r] = 0.0f;

    float m_run[2] = {-1e30f, -1e30f};
    float l_run[2] = {0.0f, 0.0f};

    const uint32_t sK = (uint32_t)__cvta_generic_to_shared(Ksm);
    const uint32_t sV = (uint32_t)__cvta_generic_to_shared(Vsm);

    // prefetch KV tile 0 into buffer 0
#pragma unroll
    for (int i = 0; i < 4; i++) {
        const int row = lr + 16 * i;
        cp16(sK + (uint32_t)(row * KST + lc) * 4u,
             K + base + (size_t)row * DM + lc);
        cp16(sV + (uint32_t)(row * VST + lc) * 4u,
             V + base + (size_t)row * DM + lc);
    }
    CP_COMMIT();

    const int NT = TLEN / 64;
    for (int tk = 0; tk < NT; tk++) {
        const int cur = tk & 1;
        __syncthreads();   // all reads of buf cur^1 (iter tk-1) done; Q stores visible (tk=0)
        if (tk + 1 < NT) {
            const int kv1 = (tk + 1) * 64;
            const uint32_t ko = (uint32_t)((cur ^ 1) * KBUF) * 4u;
            const uint32_t vo = (uint32_t)((cur ^ 1) * VBUF) * 4u;
#pragma unroll
            for (int i = 0; i < 4; i++) {
                const int row = lr + 16 * i;
                cp16(sK + ko + (uint32_t)(row * KST + lc) * 4u,
                     K + base + (size_t)(kv1 + row) * DM + lc);
                cp16(sV + vo + (uint32_t)(row * VST + lc) * 4u,
                     V + base + (size_t)(kv1 + row) * DM + lc);
            }
            CP_COMMIT();
            CP_WAIT1();    // tile tk complete; tk+1 in flight
        } else {
            CP_WAIT0();
        }
        __syncthreads();   // tile cur visible to all

        const float* Kb = Ksm + cur * KBUF;
        const float* Vb = Vsm + cur * VBUF;

        // ---- S = Q K^T  (16 x 64 per warp) ----
        float sf[8][4];
#pragma unroll
        for (int nt = 0; nt < 8; nt++)
#pragma unroll
            for (int r = 0; r < 4; r++) sf[nt][r] = 0.0f;

#pragma unroll
        for (int kc = 0; kc < 8; kc++) {
            const int kk = kc * 8;
            uint32_t qf[4], kb[8][2];
            {
                const float* p = Qs + (mw + g) * QST + kk + t;
                qf[0] = __float_as_uint(p[0]);
                qf[1] = __float_as_uint(p[8 * QST]);
                qf[2] = __float_as_uint(p[4]);
                qf[3] = __float_as_uint(p[8 * QST + 4]);
            }
#pragma unroll
            for (int nt = 0; nt < 8; nt++) {
                const float* p = Kb + (nt * 8 + g) * KST + kk + t;
                kb[nt][0] = __float_as_uint(p[0]);
                kb[nt][1] = __float_as_uint(p[4]);
            }
#pragma unroll
            for (int nt = 0; nt < 8; nt++)
                MMA_TF32(sf[nt], qf, kb[nt]);
        }

        // ---- online softmax (warp-private rows mw+g, mw+8+g) ----
#pragma unroll
        for (int rh = 0; rh < 2; rh++) {
            float mx = -1e30f;
#pragma unroll
            for (int nt = 0; nt < 8; nt++)
                mx = fmaxf(mx, fmaxf(sf[nt][rh * 2], sf[nt][rh * 2 + 1]));
            mx = fmaxf(mx, __shfl_xor_sync(0xffffffffu, mx, 1));
            mx = fmaxf(mx, __shfl_xor_sync(0xffffffffu, mx, 2));
            const float newm = fmaxf(m_run[rh], mx);
            const float fac  = __expf(m_run[rh] - newm);
            float sum = 0.0f;
            float* prow = Psm + (mw + rh * 8 + g) * PST + 2 * t;
#pragma unroll
            for (int nt = 0; nt < 8; nt++) {
                const float p0 = __expf(sf[nt][rh * 2]     - newm);
                const float p1 = __expf(sf[nt][rh * 2 + 1] - newm);
                sum += p0 + p1;
                prow[nt * 8]     = f2tf32(p0);
                prow[nt * 8 + 1] = f2tf32(p1);
            }
            sum += __shfl_xor_sync(0xffffffffu, sum, 1);
            sum += __shfl_xor_sync(0xffffffffu, sum, 2);
            l_run[rh] = l_run[rh] * fac + sum;
            m_run[rh] = newm;
#pragma unroll
            for (int nt = 0; nt < 8; nt++) {
                of[nt][rh * 2]     *= fac;
                of[nt][rh * 2 + 1] *= fac;
            }
        }
        __syncwarp();   // P rows warp-private: order STS -> LDS within warp

        // ---- O += P V ----
#pragma unroll
        for (int kc = 0; kc < 8; kc++) {
            const int kk = kc * 8;
            uint32_t pf[4], vb[8][2];
            {
                const float* p = Psm + (mw + g) * PST + kk + t;
                pf[0] = __float_as_uint(p[0]);
                pf[1] = __float_as_uint(p[8 * PST]);
                pf[2] = __float_as_uint(p[4]);
                pf[3] = __float_as_uint(p[8 * PST + 4]);
            }
#pragma unroll
            for (int nt = 0; nt < 8; nt++) {
                const float* p = Vb + (kk + t) * VST + nt * 8 + g;
                vb[nt][0] = __float_as_uint(p[0]);
                vb[nt][1] = __float_as_uint(p[4 * VST]);
            }
#pragma unroll
            for (int nt = 0; nt < 8; nt++)
                MMA_TF32(of[nt], pf, vb[nt]);
        }
    }

    // ---- epilogue (includes batch offset via `base`) ----
#pragma unroll
    for (int rh = 0; rh < 2; rh++) {
        const float inv = 1.0f / l_run[rh];
        const int rloc = q0 + mw + rh * 8 + g;
        float* Op = O + base + (size_t)rloc * DM;
#pragma unroll
        for (int nt = 0; nt < 8; nt++) {
            const float a0 = f2tf32(of[nt][rh * 2] * inv);
            const float a1 = f2tf32(of[nt][rh * 2 + 1] * inv);
            *(float2*)&Op[nt * 8 + 2 * t] = make_float2(a0, a1);
        }
    }
}

// ---------------------------------------------------------------------------
// Launch: cvt -> fused QKV GEMM -> tf32 flash -> output GEMM
// ---------------------------------------------------------------------------
extern "C" void kernel_launch(void* const* d_in, const int* in_sizes, int n_in,
                              void* d_out, int out_size)
{
    (void)in_sizes; (void)n_in; (void)out_size;
    const float* x  = (const float*)d_in[0];
    const float* Wq = (const float*)d_in[1];
    const float* Wk = (const float*)d_in[2];
    const float* Wv = (const float*)d_in[3];
    const float* Wo = (const float*)d_in[4];
    float* out = (float*)d_out;

    float *q, *k, *v, *ot, *xc, *wq, *wk, *wv, *wo;
    cudaGetSymbolAddress((void**)&q,  g_q);
    cudaGetSymbolAddress((void**)&k,  g_k);
    cudaGetSymbolAddress((void**)&v,  g_v);
    cudaGetSymbolAddress((void**)&ot, g_ot);
    cudaGetSymbolAddress((void**)&xc, g_xc);
    cudaGetSymbolAddress((void**)&wq, g_wq);
    cudaGetSymbolAddress((void**)&wk, g_wk);
    cudaGetSymbolAddress((void**)&wv, g_wv);
    cudaGetSymbolAddress((void**)&wo, g_wo);

    const int gemm_smem = 4 * GBUF * (int)sizeof(float);  // 73728

    cudaFuncSetAttribute(gemm_tf32<true, true>,
                         cudaFuncAttributeMaxDynamicSharedMemorySize, gemm_smem);
    cudaFuncSetAttribute(gemm_tf32<false, false>,
                         cudaFuncAttributeMaxDynamicSharedMemorySize, gemm_smem);
    cudaFuncSetAttribute(flash_tf32,
                         cudaFuncAttributeMaxDynamicSharedMemorySize, FLASH_SMEM);
    cudaFuncSetAttribute(gemm_tf32<true, true>,
                         cudaFuncAttributePreferredSharedMemoryCarveout, 100);
    cudaFuncSetAttribute(gemm_tf32<false, false>,
                         cudaFuncAttributePreferredSharedMemoryCarveout, 100);
    cudaFuncSetAttribute(flash_tf32,
                         cudaFuncAttributePreferredSharedMemoryCarveout, 100);

    cvt_tf32_kernel<<<(BT * DM / 4 + 255) / 256, 256>>>((const float4*)x,  (float4*)xc, BT * DM / 4);
    cvt_tf32_kernel<<<(DM * DM / 4 + 255) / 256, 256>>>((const float4*)Wq, (float4*)wq, DM * DM / 4);
    cvt_tf32_kernel<<<(DM * DM / 4 + 255) / 256, 256>>>((const float4*)Wk, (float4*)wk, DM * DM / 4);
    cvt_tf32_kernel<<<(DM * DM / 4 + 255) / 256, 256>>>((const float4*)Wv, (float4*)wv, DM * DM / 4);
    cvt_tf32_kernel<<<(DM * DM / 4 + 255) / 256, 256>>>((const float4*)Wo, (float4*)wo, DM * DM / 4);

    // fused QKV projection: grid.z selects (W, C)
    dim3 gq(DM / 128, BT / 128, 3);  // (8, 32, 3)
    gemm_tf32<true, true><<<gq, 128, gemm_smem>>>(xc, wq, wk, wv, q, k, v, BT, DM, DM);

    // tf32 tensor-core flash attention (verified R9)
    flash_tf32<<<dim3(TLEN / 128, NH, BATCH), 256, FLASH_SMEM>>>(q, k, v, ot);

    // output projection
    dim3 gg(DM / 128, BT / 128);     // (8, 32)
    gemm_tf32<false, false><<<gg, 128, gemm_smem>>>(ot, wo, nullptr, nullptr, out, nullptr, nullptr, BT, DM, DM);
}

// round 13
// speedup vs baseline: 3.3391x; 1.1527x over previous
#include <cuda_runtime.h>
#include <stdint.h>
#include <stddef.h>
#include <math.h>

#define BATCH 2
#define TLEN  2048
#define DM    1024
#define NH    16
#define DHD   64
#define BT    (BATCH * TLEN)   // 4096

// ---------------------------------------------------------------------------
// Scratch (allocation-free rule: __device__ globals)
// ---------------------------------------------------------------------------
__device__ float g_q[BT * DM];
__device__ float g_k[BT * DM];
__device__ float g_v[BT * DM];
__device__ float g_ot[BT * DM];
__device__ float g_xc[BT * DM];
__device__ float g_wq[DM * DM];
__device__ float g_wk[DM * DM];
__device__ float g_wv[DM * DM];
__device__ float g_wo[DM * DM];

// ---------------------------------------------------------------------------
// Helpers
// ---------------------------------------------------------------------------
__device__ __forceinline__ float f2tf32(float x) {
    uint32_t u;
    asm("cvt.rna.tf32.f32 %0, %1;" : "=r"(u) : "f"(x));
    return __uint_as_float(u);
}

__device__ __forceinline__ void cp16(uint32_t smem, const void* gmem) {
    asm volatile("cp.async.cg.shared.global [%0], [%1], 16;"
                 :: "r"(smem), "l"(gmem));
}
#define CP_COMMIT() asm volatile("cp.async.commit_group;")
#define CP_WAIT0()  asm volatile("cp.async.wait_group 0;")
#define CP_WAIT1()  asm volatile("cp.async.wait_group 1;")

// mma.sync m16n8k8 tf32 (layouts hardware-verified R6/R9)
#define MMA_TF32(d, a, b)                                                   \
    asm volatile(                                                           \
        "mma.sync.aligned.m16n8k8.row.col.f32.tf32.tf32.f32 "               \
        "{%0,%1,%2,%3},{%4,%5,%6,%7},{%8,%9},{%0,%1,%2,%3};"                \
        : "+f"((d)[0]), "+f"((d)[1]), "+f"((d)[2]), "+f"((d)[3])            \
        : "r"((a)[0]), "r"((a)[1]), "r"((a)[2]), "r"((a)[3]),               \
          "r"((b)[0]), "r"((b)[1]))

// ---------------------------------------------------------------------------
// Prep: round fp32 -> tf32 (RN)
// ---------------------------------------------------------------------------
__global__ void cvt_tf32_kernel(const float4* __restrict__ in,
                                float4* __restrict__ out, int n4) {
    int i = blockIdx.x * blockDim.x + threadIdx.x;
    if (i < n4) {
        float4 v = in[i];
        v.x = f2tf32(v.x); v.y = f2tf32(v.y);
        v.z = f2tf32(v.z); v.w = f2tf32(v.w);
        out[i] = v;
    }
}

// batched: z selects one of 4 weight matrices
__global__ void cvt_tf32_w4(const float4* __restrict__ i0, float4* __restrict__ o0,
                            const float4* __restrict__ i1, float4* __restrict__ o1,
                            const float4* __restrict__ i2, float4* __restrict__ o2,
                            const float4* __restrict__ i3, float4* __restrict__ o3,
                            int n4) {
    const float4* in = i0; float4* out = o0;
    if (blockIdx.z == 1) { in = i1; out = o1; }
    else if (blockIdx.z == 2) { in = i2; out = o2; }
    else if (blockIdx.z == 3) { in = i3; out = o3; }
    int i = blockIdx.x * blockDim.x + threadIdx.x;
    if (i < n4) {
        float4 v = in[i];
        v.x = f2tf32(v.x); v.y = f2tf32(v.y);
        v.z = f2tf32(v.z); v.w = f2tf32(v.w);
        out[i] = v;
    }
}

// ---------------------------------------------------------------------------
// tf32 GEMM v2 (NT): C[m,n] = sum_k A[m,k]*B[n,k]
// 256 threads (8 warps, 2x4 of 64x64), tile 128x256, BK=32, double-buffered.
// Inner loop & fragment indexing identical to the hardware-verified R6 code.
// ---------------------------------------------------------------------------
#define GS    36
#define ABUF  (128 * GS)
#define BBUF  (256 * GS)
#define GEMM_SMEM ((2 * ABUF + 2 * BBUF) * 4)   // 110592

template <bool CVT_OUT, bool QKV>
__global__ __launch_bounds__(256)
void gemm_tf32(const float* __restrict__ A,
               const float* __restrict__ B0, const float* __restrict__ B1,
               const float* __restrict__ B2,
               float* __restrict__ C0, float* __restrict__ C1,
               float* __restrict__ C2,
               int M, int N, int K)
{
    const float* B = B0;
    float* C = C0;
    if (QKV) {
        if (blockIdx.z == 1) { B = B1; C = C1; }
        else if (blockIdx.z == 2) { B = B2; C = C2; }
    }

    extern __shared__ float sm[];
    float* As = sm;                 // [2][ABUF]
    float* Bs = sm + 2 * ABUF;      // [2][BBUF]

    const int tid  = threadIdx.x;
    const int lane = tid & 31;
    const int warp = tid >> 5;             // 0..7
    const int g    = lane >> 2;
    const int t    = lane & 3;
    const int m0   = blockIdx.y * 128;
    const int n0   = blockIdx.x * 256;
    const int mw   = (warp >> 2) * 64;     // 0,64
    const int nw   = (warp & 3) * 64;      // 0,64,128,192

    const int lr = tid >> 3;               // 0..31
    const int lc = (tid & 7) << 2;         // 0..28
    const float* Ag = A + (size_t)(m0 + lr) * K + lc;
    const float* Bg = B + (size_t)(n0 + lr) * K + lc;

    const uint32_t sA = (uint32_t)__cvta_generic_to_shared(As);
    const uint32_t sB = (uint32_t)__cvta_generic_to_shared(Bs);
    const uint32_t soff = (uint32_t)(lr * GS + lc) * 4u;

    float acc[4][8][4];
#pragma unroll
    for (int mt = 0; mt < 4; mt++)
#pragma unroll
        for (int nt = 0; nt < 8; nt++)
#pragma unroll
            for (int r = 0; r < 4; r++) acc[mt][nt][r] = 0.0f;

    const int nkt = K >> 5;

    // prefetch tile 0: A 128 rows (4 passes), B 256 rows (8 passes)
#pragma unroll
    for (int i = 0; i < 4; i++)
        cp16(sA + soff + (uint32_t)(i * 32 * GS * 4), Ag + (size_t)i * 32 * K);
#pragma unroll
    for (int i = 0; i < 8; i++)
        cp16(sB + soff + (uint32_t)(i * 32 * GS * 4), Bg + (size_t)i * 32 * K);
    CP_COMMIT();

    for (int kt = 0; kt < nkt; kt++) {
        const int cur = kt & 1;
        if (kt + 1 < nkt) {
            const int nxt = cur ^ 1;
            const float* Ap = Ag + (size_t)(kt + 1) * 32;
            const float* Bp = Bg + (size_t)(kt + 1) * 32;
            const uint32_t ao = (uint32_t)(nxt * ABUF) * 4u;
            const uint32_t bo = (uint32_t)(nxt * BBUF) * 4u;
#pragma unroll
            for (int i = 0; i < 4; i++)
                cp16(sA + ao + soff + (uint32_t)(i * 32 * GS * 4), Ap + (size_t)i * 32 * K);
#pragma unroll
            for (int i = 0; i < 8; i++)
                cp16(sB + bo + soff + (uint32_t)(i * 32 * GS * 4), Bp + (size_t)i * 32 * K);
            CP_COMMIT();
            CP_WAIT1();
        } else {
            CP_WAIT0();
        }
        __syncthreads();

        const float* Ab = As + cur * ABUF + mw * GS;
        const float* Bb = Bs + cur * BBUF + nw * GS;
#pragma unroll
        for (int kc = 0; kc < 4; kc++) {
            const int kk = kc * 8;
            uint32_t af[4][4], bf[8][2];
#pragma unroll
            for (int mt = 0; mt < 4; mt++) {
                const float* p = Ab + (mt * 16 + g) * GS + kk + t;
                af[mt][0] = __float_as_uint(p[0]);
                af[mt][1] = __float_as_uint(p[8 * GS]);
                af[mt][2] = __float_as_uint(p[4]);
                af[mt][3] = __float_as_uint(p[8 * GS + 4]);
            }
#pragma unroll
            for (int nt = 0; nt < 8; nt++) {
                const float* p = Bb + (nt * 8 + g) * GS + kk + t;
                bf[nt][0] = __float_as_uint(p[0]);
                bf[nt][1] = __float_as_uint(p[4]);
            }
#pragma unroll
            for (int mt = 0; mt < 4; mt++)
#pragma unroll
                for (int nt = 0; nt < 8; nt++)
                    MMA_TF32(acc[mt][nt], af[mt], bf[nt]);
        }
        __syncthreads();
    }

#pragma unroll
    for (int mt = 0; mt < 4; mt++) {
#pragma unroll
        for (int nt = 0; nt < 8; nt++) {
            const int row = m0 + mw + mt * 16 + g;
            const int col = n0 + nw + nt * 8 + 2 * t;
            float2 v0, v1;
            if (CVT_OUT) {
                v0 = make_float2(f2tf32(acc[mt][nt][0]), f2tf32(acc[mt][nt][1]));
                v1 = make_float2(f2tf32(acc[mt][nt][2]), f2tf32(acc[mt][nt][3]));
            } else {
                v0 = make_float2(acc[mt][nt][0], acc[mt][nt][1]);
                v1 = make_float2(acc[mt][nt][2], acc[mt][nt][3]);
            }
            *(float2*)&C[(size_t)row * N + col]       = v0;
            *(float2*)&C[(size_t)(row + 8) * N + col] = v1;
        }
    }
}

// ---------------------------------------------------------------------------
// tf32 flash attention v3: 256 threads (8 warps x 32 Q-rows), Q tile 256,
// KV tile 64 double-buffered. Per-warp body = hardware-verified R9 (mt=2);
// pipeline = hardware-verified R11.
// ---------------------------------------------------------------------------
#define QST 68
#define KST 68
#define VST 72
#define PST 68
#define KBUF (64 * KST)
#define VBUF (64 * VST)
#define QROWS 256
#define FLASH_SMEM ((QROWS * QST + 2 * KBUF + 2 * VBUF + QROWS * PST) * 4)  // 210944

__global__ __launch_bounds__(256)
void flash_tf32(const float* __restrict__ Q, const float* __restrict__ K,
                const float* __restrict__ V, float* __restrict__ O)
{
    extern __shared__ float sm[];
    float* Qs  = sm;                       // [256][QST]
    float* Ksm = Qs + QROWS * QST;         // [2][64][KST]
    float* Vsm = Ksm + 2 * KBUF;           // [2][64][VST]
    float* Psm = Vsm + 2 * VBUF;           // [256][PST]

    const int tid  = threadIdx.x;
    const int lane = tid & 31;
    const int warp = tid >> 5;             // 0..7
    const int g    = lane >> 2;
    const int t    = lane & 3;
    const int q0   = blockIdx.x * QROWS;
    const int h    = blockIdx.y;
    const int b    = blockIdx.z;
    const size_t base = (size_t)b * TLEN * DM + (size_t)h * DHD;

    const int lr = tid >> 4;               // 0..15
    const int lc = (tid & 15) << 2;        // 0..60

    // load Q tile (256 x 64), pre-scaled by 1/sqrt(64)
#pragma unroll
    for (int i = 0; i < 16; i++) {
        const int row = lr + 16 * i;
        float4 v = *(const float4*)(Q + base + (size_t)(q0 + row) * DM + lc);
        v.x *= 0.125f; v.y *= 0.125f; v.z *= 0.125f; v.w *= 0.125f;
        *(float4*)&Qs[row * QST + lc] = v;
    }

    const int mw = warp * 32;              // 32 Q-rows per warp

    float of[2][8][4];
#pragma unroll
    for (int mt = 0; mt < 2; mt++)
#pragma unroll
        for (int nt = 0; nt < 8; nt++)
#pragma unroll
            for (int r = 0; r < 4; r++) of[mt][nt][r] = 0.0f;

    float m_run[2][2] = {{-1e30f, -1e30f}, {-1e30f, -1e30f}};
    float l_run[2][2] = {{0.0f, 0.0f}, {0.0f, 0.0f}};

    const uint32_t sK = (uint32_t)__cvta_generic_to_shared(Ksm);
    const uint32_t sV = (uint32_t)__cvta_generic_to_shared(Vsm);

    // prefetch KV tile 0 into buffer 0 (64 rows, 4 passes)
#pragma unroll
    for (int i = 0; i < 4; i++) {
        const int row = lr + 16 * i;
        cp16(sK + (uint32_t)(row * KST + lc) * 4u, K + base + (size_t)row * DM + lc);
        cp16(sV + (uint32_t)(row * VST + lc) * 4u, V + base + (size_t)row * DM + lc);
    }
    CP_COMMIT();

    const int NT = TLEN / 64;
    for (int tk = 0; tk < NT; tk++) {
        const int cur = tk & 1;
        __syncthreads();   // reads of buf cur^1 (iter tk-1) done; Q visible at tk=0
        if (tk + 1 < NT) {
            const int kv1 = (tk + 1) * 64;
            const uint32_t ko = (uint32_t)((cur ^ 1) * KBUF) * 4u;
            const uint32_t vo = (uint32_t)((cur ^ 1) * VBUF) * 4u;
#pragma unroll
            for (int i = 0; i < 4; i++) {
                const int row = lr + 16 * i;
                cp16(sK + ko + (uint32_t)(row * KST + lc) * 4u,
                     K + base + (size_t)(kv1 + row) * DM + lc);
                cp16(sV + vo + (uint32_t)(row * VST + lc) * 4u,
                     V + base + (size_t)(kv1 + row) * DM + lc);
            }
            CP_COMMIT();
            CP_WAIT1();
        } else {
            CP_WAIT0();
        }
        __syncthreads();

        const float* Kb = Ksm + cur * KBUF;
        const float* Vb = Vsm + cur * VBUF;

        // ---- S = Q K^T  (32 x 64 per warp) ----
        float sf[2][8][4];
#pragma unroll
        for (int mt = 0; mt < 2; mt++)
#pragma unroll
            for (int nt = 0; nt < 8; nt++)
#pragma unroll
                for (int r = 0; r < 4; r++) sf[mt][nt][r] = 0.0f;

#pragma unroll
        for (int kc = 0; kc < 8; kc++) {
            const int kk = kc * 8;
            uint32_t qf[2][4], kb[8][2];
#pragma unroll
            for (int mt = 0; mt < 2; mt++) {
                const float* p = Qs + (mw + mt * 16 + g) * QST + kk + t;
                qf[mt][0] = __float_as_uint(p[0]);
                qf[mt][1] = __float_as_uint(p[8 * QST]);
                qf[mt][2] = __float_as_uint(p[4]);
                qf[mt][3] = __float_as_uint(p[8 * QST + 4]);
            }
#pragma unroll
            for (int nt = 0; nt < 8; nt++) {
                const float* p = Kb + (nt * 8 + g) * KST + kk + t;
                kb[nt][0] = __float_as_uint(p[0]);
                kb[nt][1] = __float_as_uint(p[4]);
            }
#pragma unroll
            for (int mt = 0; mt < 2; mt++)
#pragma unroll
                for (int nt = 0; nt < 8; nt++)
                    MMA_TF32(sf[mt][nt], qf[mt], kb[nt]);
        }

        // ---- online softmax (rows warp-private; quad shares a row) ----
#pragma unroll
        for (int mt = 0; mt < 2; mt++) {
#pragma unroll
            for (int rh = 0; rh < 2; rh++) {
                float mx = -1e30f;
#pragma unroll
                for (int nt = 0; nt < 8; nt++)
                    mx = fmaxf(mx, fmaxf(sf[mt][nt][rh * 2], sf[mt][nt][rh * 2 + 1]));
                mx = fmaxf(mx, __shfl_xor_sync(0xffffffffu, mx, 1));
                mx = fmaxf(mx, __shfl_xor_sync(0xffffffffu, mx, 2));
                const float newm = fmaxf(m_run[mt][rh], mx);
                const float fac  = __expf(m_run[mt][rh] - newm);
                float sum = 0.0f;
                float* prow = Psm + (mw + mt * 16 + rh * 8 + g) * PST + 2 * t;
#pragma unroll
                for (int nt = 0; nt < 8; nt++) {
                    const float p0 = __expf(sf[mt][nt][rh * 2]     - newm);
                    const float p1 = __expf(sf[mt][nt][rh * 2 + 1] - newm);
                    sum += p0 + p1;
                    prow[nt * 8]     = f2tf32(p0);
                    prow[nt * 8 + 1] = f2tf32(p1);
                }
                sum += __shfl_xor_sync(0xffffffffu, sum, 1);
                sum += __shfl_xor_sync(0xffffffffu, sum, 2);
                l_run[mt][rh] = l_run[mt][rh] * fac + sum;
                m_run[mt][rh] = newm;
#pragma unroll
                for (int nt = 0; nt < 8; nt++) {
                    of[mt][nt][rh * 2]     *= fac;
                    of[mt][nt][rh * 2 + 1] *= fac;
                }
            }
        }
        __syncwarp();   // P rows warp-private: order STS -> LDS within warp

        // ---- O += P V ----
#pragma unroll
        for (int kc = 0; kc < 8; kc++) {
            const int kk = kc * 8;
            uint32_t pf[2][4], vb[8][2];
#pragma unroll
            for (int mt = 0; mt < 2; mt++) {
                const float* p = Psm + (mw + mt * 16 + g) * PST + kk + t;
                pf[mt][0] = __float_as_uint(p[0]);
                pf[mt][1] = __float_as_uint(p[8 * PST]);
                pf[mt][2] = __float_as_uint(p[4]);
                pf[mt][3] = __float_as_uint(p[8 * PST + 4]);
            }
#pragma unroll
            for (int nt = 0; nt < 8; nt++) {
                const float* p = Vb + (kk + t) * VST + nt * 8 + g;
                vb[nt][0] = __float_as_uint(p[0]);
                vb[nt][1] = __float_as_uint(p[4 * VST]);
            }
#pragma unroll
            for (int mt = 0; mt < 2; mt++)
#pragma unroll
                for (int nt = 0; nt < 8; nt++)
                    MMA_TF32(of[mt][nt], pf[mt], vb[nt]);
        }
    }

    // ---- epilogue (batch offset via `base`) ----
#pragma unroll
    for (int mt = 0; mt < 2; mt++) {
#pragma unroll
        for (int rh = 0; rh < 2; rh++) {
            const float inv = 1.0f / l_run[mt][rh];
            const int rloc = q0 + mw + mt * 16 + rh * 8 + g;
            float* Op = O + base + (size_t)rloc * DM;
#pragma unroll
            for (int nt = 0; nt < 8; nt++) {
                const float a0 = f2tf32(of[mt][nt][rh * 2] * inv);
                const float a1 = f2tf32(of[mt][nt][rh * 2 + 1] * inv);
                *(float2*)&Op[nt * 8 + 2 * t] = make_float2(a0, a1);
            }
        }
    }
}

// ---------------------------------------------------------------------------
// Launch
// ---------------------------------------------------------------------------
extern "C" void kernel_launch(void* const* d_in, const int* in_sizes, int n_in,
                              void* d_out, int out_size)
{
    (void)in_sizes; (void)n_in; (void)out_size;
    const float* x  = (const float*)d_in[0];
    const float* Wq = (const float*)d_in[1];
    const float* Wk = (const float*)d_in[2];
    const float* Wv = (const float*)d_in[3];
    const float* Wo = (const float*)d_in[4];
    float* out = (float*)d_out;

    float *q, *k, *v, *ot, *xc, *wq, *wk, *wv, *wo;
    cudaGetSymbolAddress((void**)&q,  g_q);
    cudaGetSymbolAddress((void**)&k,  g_k);
    cudaGetSymbolAddress((void**)&v,  g_v);
    cudaGetSymbolAddress((void**)&ot, g_ot);
    cudaGetSymbolAddress((void**)&xc, g_xc);
    cudaGetSymbolAddress((void**)&wq, g_wq);
    cudaGetSymbolAddress((void**)&wk, g_wk);
    cudaGetSymbolAddress((void**)&wv, g_wv);
    cudaGetSymbolAddress((void**)&wo, g_wo);

    cudaFuncSetAttribute(gemm_tf32<true, true>,
                         cudaFuncAttributeMaxDynamicSharedMemorySize, GEMM_SMEM);
    cudaFuncSetAttribute(gemm_tf32<false, false>,
                         cudaFuncAttributeMaxDynamicSharedMemorySize, GEMM_SMEM);
    cudaFuncSetAttribute(flash_tf32,
                         cudaFuncAttributeMaxDynamicSharedMemorySize, FLASH_SMEM);
    cudaFuncSetAttribute(gemm_tf32<true, true>,
                         cudaFuncAttributePreferredSharedMemoryCarveout, 100);
    cudaFuncSetAttribute(gemm_tf32<false, false>,
                         cudaFuncAttributePreferredSharedMemoryCarveout, 100);
    cudaFuncSetAttribute(flash_tf32,
                         cudaFuncAttributePreferredSharedMemoryCarveout, 100);

    // tf32-round inputs: x, then all 4 weights in one batched launch
    cvt_tf32_kernel<<<(BT * DM / 4 + 255) / 256, 256>>>((const float4*)x, (float4*)xc, BT * DM / 4);
    {
        dim3 gw((DM * DM / 4 + 255) / 256, 1, 4);
        cvt_tf32_w4<<<gw, 256>>>((const float4*)Wq, (float4*)wq,
                                 (const float4*)Wk, (float4*)wk,
                                 (const float4*)Wv, (float4*)wv,
                                 (const float4*)Wo, (float4*)wo,
                                 DM * DM / 4);
    }

    // fused QKV projection: tile 128x256, grid.z selects (W, C)
    dim3 gq(DM / 256, BT / 128, 3);  // (4, 32, 3)
    gemm_tf32<true, true><<<gq, 256, GEMM_SMEM>>>(xc, wq, wk, wv, q, k, v, BT, DM, DM);

    // tf32 flash attention, Q-tile 256
    flash_tf32<<<dim3(TLEN / QROWS, NH, BATCH), 256, FLASH_SMEM>>>(q, k, v, ot);

    // output projection
    dim3 gg(DM / 256, BT / 128, 1);  // (4, 32)
    gemm_tf32<false, false><<<gg, 256, GEMM_SMEM>>>(ot, wo, nullptr, nullptr, out, nullptr, nullptr, BT, DM, DM);
}